// round 13
// baseline (speedup 1.0000x reference)
#include <cuda_runtime.h>
#include <cstdint>

#define NQ     6
#define BATCH  256
#define SEQ    512
#define FULLM  0xffffffffu
#define PI_F   3.14159265358979323846f
#define SH(v,m) __shfl_xor_sync(FULLM, (v), (m))

// ---------------- scratch ----------------
__device__ float4 g_pk [BATCH * SEQ * 3];   // [dta0..3][dta4,5,xdt0,1][xdt2..5]
__device__ float  g_cw [BATCH * SEQ * 18];
__device__ float  g_tf [24];
__device__ float2 g_fa [12];   // trio alpha (L*6+i)
__device__ float2 g_fb [12];   // trio beta
__device__ float2 g_crx[24];   // (cos,sin) half-angle: L*12 + [0..5 up][6..11 down]

// ---------------- prep 1 ----------------
__global__ void prep_kernel(const float* __restrict__ angles,
                            const float* __restrict__ Wx,
                            const float* __restrict__ Wdt,
                            const float* __restrict__ bdt,
                            const float* __restrict__ Wc) {
    int idx = blockIdx.x * blockDim.x + threadIdx.x;
    if (idx >= BATCH * SEQ) return;
    float a[6];
#pragma unroll
    for (int k = 0; k < 6; ++k) a[k] = angles[idx * 6 + k];
    float dtr[3];
#pragma unroll
    for (int r = 0; r < 3; ++r) {
        float s = 0.f;
#pragma unroll
        for (int k = 0; k < 6; ++k) s += a[k] * Wx[r * 6 + k];
        dtr[r] = s;
    }
    float C[6];
#pragma unroll
    for (int j = 0; j < 6; ++j) {
        float s = 0.f;
#pragma unroll
        for (int k = 0; k < 6; ++k) s += a[k] * Wx[(9 + j) * 6 + k];
        C[j] = s;
    }
    float dta[6];
#pragma unroll
    for (int i = 0; i < 6; ++i) {
        float v = bdt[i];
#pragma unroll
        for (int r = 0; r < 3; ++r) v += dtr[r] * Wdt[i * 3 + r];
        float sp = (v > 20.f) ? v : log1pf(expf(v));
        dta[i] = tanhf(sp) * PI_F;
    }
    g_pk[idx * 3 + 0] = make_float4(dta[0], dta[1], dta[2], dta[3]);
    g_pk[idx * 3 + 1] = make_float4(dta[4], dta[5], a[0] * dta[0], a[1] * dta[1]);
    g_pk[idx * 3 + 2] = make_float4(a[2] * dta[2], a[3] * dta[3], a[4] * dta[4], a[5] * dta[5]);
#pragma unroll
    for (int j = 0; j < 18; ++j) {
        float s = 0.f;
#pragma unroll
        for (int k = 0; k < 6; ++k) s += C[k] * Wc[j * 6 + k];
        g_cw[idx * 18 + j] = s;
    }
}

// ---------------- prep 2 ----------------
__global__ void prep2_kernel(const float* __restrict__ pc,
                             const float* __restrict__ qp,
                             const float* __restrict__ cp) {
    int t = threadIdx.x;
    if (t < 24) {
        int d = t / 6, i = t % 6;
        g_tf[t] = pc[d] * PI_F * ((d < 3) ? qp[d * 6 + i] : 1.0f);
    }
    if (t < 24) {
        int L = t / 12, k = t % 12;
        float ang = (k < 6) ? cp[L * 30 + 18 + k] : cp[L * 30 + 24 + (k - 6)];
        float th = 0.5f * ang;
        g_crx[t] = make_float2(cosf(th), sinf(th));
    }
    if (t < 12) {   // U = RZ(c)*RY(b)*RX(a), half angles
        int L = t / 6, i = t % 6, base = L * 30 + i * 3;
        float cx = cosf(0.5f * cp[base]),     sx = sinf(0.5f * cp[base]);
        float cy = cosf(0.5f * cp[base + 1]), sy = sinf(0.5f * cp[base + 1]);
        float cz = cosf(0.5f * cp[base + 2]), sz = sinf(0.5f * cp[base + 2]);
        float M00r = cy * cx, M00i = sy * sx;
        float M10r = sy * cx, M10i = -cy * sx;
        g_fa[t] = make_float2(cz * M00r + sz * M00i, cz * M00i - sz * M00r);
        g_fb[t] = make_float2(cz * M10r - sz * M10i, cz * M10i + sz * M10r);
    }
}

// ---------------- complex / matrix helpers (prologue only) ----------------
__device__ __forceinline__ float2 cmul2(float2 a, float2 b) {
    return make_float2(a.x*b.x - a.y*b.y, a.x*b.y + a.y*b.x);
}
__device__ __forceinline__ float2 cadd2(float2 a, float2 b) {
    return make_float2(a.x + b.x, a.y + b.y);
}
struct M2 { float2 m[2][2]; };
__device__ __forceinline__ M2 mkT(float2 al, float2 be) {
    M2 t;
    t.m[0][0] = al; t.m[0][1] = make_float2(-be.x, be.y);
    t.m[1][0] = be; t.m[1][1] = make_float2(al.x, -al.y);
    return t;
}
__device__ __forceinline__ M2 mkRX(float c, float s) {
    M2 t;
    t.m[0][0] = make_float2(c, 0.f); t.m[0][1] = make_float2(0.f, -s);
    t.m[1][0] = make_float2(0.f, -s); t.m[1][1] = make_float2(c, 0.f);
    return t;
}
__device__ __forceinline__ void kron4(float2 G[4][4], const M2& A, const M2& B) {
#pragma unroll
    for (int i = 0; i < 2; ++i)
#pragma unroll
    for (int j = 0; j < 2; ++j)
#pragma unroll
    for (int k = 0; k < 2; ++k)
#pragma unroll
    for (int l = 0; l < 2; ++l)
        G[2*i + k][2*j + l] = cmul2(A.m[i][j], B.m[k][l]);
}
__device__ __forceinline__ void ctrlH_mul(float2 G[4][4], const M2& R) {
#pragma unroll
    for (int c = 0; c < 4; ++c) {
        float2 t2 = G[2][c], t3 = G[3][c];
        G[2][c] = cadd2(cmul2(R.m[0][0], t2), cmul2(R.m[0][1], t3));
        G[3][c] = cadd2(cmul2(R.m[1][0], t2), cmul2(R.m[1][1], t3));
    }
}
__device__ __forceinline__ void tgtH_mul(float2 G[4][4], const M2& R) {
#pragma unroll
    for (int c = 0; c < 4; ++c) {
#pragma unroll
        for (int aL = 0; aL < 2; ++aL) {
            float2 t0 = G[aL][c], t1 = G[2 + aL][c];
            G[aL][c]     = cadd2(cmul2(R.m[0][0], t0), cmul2(R.m[0][1], t1));
            G[2 + aL][c] = cadd2(cmul2(R.m[1][0], t0), cmul2(R.m[1][1], t1));
        }
    }
}
// extract one row d: O[j] = G[d][d^j]
__device__ __forceinline__ void extractRow(const float2 G[4][4], int d, float* O) {
#pragma unroll
    for (int j = 0; j < 4; ++j) {
        float2 c = (d == 0) ? G[0][j] : (d == 1) ? G[1][1^j] : (d == 2) ? G[2][2^j] : G[3][3^j];
        O[2*j] = c.x; O[2*j + 1] = c.y;
    }
}

// ---------------- main sim: TWO warps per chain, one amp per lane ----------------
__global__ void __launch_bounds__(64, 1)
sim_kernel(const float* __restrict__ angles,
           const float* __restrict__ Dv_in,
           float* __restrict__ out) {
    __shared__ float sX[6][64], sY[6][64];
    const int b    = blockIdx.x;
    const int tid  = threadIdx.x;
    const int wid  = tid >> 5;
    const int lane = tid & 31;

    // ---- permutation + per-amp QSVT phase coefficients ----
    int fwd[64];
    for (int s = 0; s < 64; ++s) {
        int q[6];
#pragma unroll
        for (int i = 0; i < 6; ++i) q[i] = (s >> (5 - i)) & 1;
        q[1]^=q[0]; q[2]^=q[1]; q[3]^=q[2]; q[4]^=q[3]; q[5]^=q[4];
        q[0]^=q[5]; q[4]^=q[5]; q[3]^=q[4]; q[2]^=q[3]; q[1]^=q[2]; q[0]^=q[1];
        int tt = 0;
#pragma unroll
        for (int i = 0; i < 6; ++i) tt |= q[i] << (5 - i);
        fwd[s] = tt;
    }
    int inv[64];
    for (int s = 0; s < 64; ++s) inv[fwd[s]] = s;

    float Bq[6] = {0,0,0,0,0,0};
    int u = tid;
    for (int k = 1; k <= 4; ++k) {
        u = inv[u];
        int d = 4 - k;
#pragma unroll
        for (int i = 0; i < 6; ++i) {
            float c = 0.5f * g_tf[d * 6 + i];
            Bq[i] += ((u >> (5 - i)) & 1) ? c : -c;
        }
    }
    const int s4 = u;

    int lb[5];
#pragma unroll
    for (int bp = 0; bp < 5; ++bp) lb[bp] = (lane >> bp) & 1;
    // qubit bits: q0=wid, q1=lb[4], q2=lb[3], q3=lb[2], q4=lb[1], q5=lb[0]

    // ---- per-thread gate coefficients ----
    float Aq[2][8], Bc[2][8], Cc[2][8];
    float dgc[8], dgs[8];
    float c0c[2], c0s[2];      // fused CRX(5,0)*CRX(1,0): RX on warp bit, per-lane angle sum
    float c5c[2], c5s[2];      // CRX(0,5): ctrl = warp bit
#pragma unroll
    for (int L = 0; L < 2; ++L) {
        M2 T0 = mkT(g_fa[L*6+0], g_fb[L*6+0]);
        M2 T1 = mkT(g_fa[L*6+1], g_fb[L*6+1]);
        M2 T2 = mkT(g_fa[L*6+2], g_fb[L*6+2]);
        M2 T3 = mkT(g_fa[L*6+3], g_fb[L*6+3]);
        M2 T4 = mkT(g_fa[L*6+4], g_fb[L*6+4]);
        M2 T5 = mkT(g_fa[L*6+5], g_fb[L*6+5]);
        float2 cs;
        cs = g_crx[L*12+0];  M2 R01  = mkRX(cs.x, cs.y);
        cs = g_crx[L*12+1];  M2 R12c = mkRX(lb[4] ? cs.x : 1.f, lb[4] ? cs.y : 0.f);
        cs = g_crx[L*12+2];  M2 R23  = mkRX(cs.x, cs.y);
        cs = g_crx[L*12+3];  M2 R34c = mkRX(lb[2] ? cs.x : 1.f, lb[2] ? cs.y : 0.f);
        cs = g_crx[L*12+4];  M2 R45  = mkRX(cs.x, cs.y);

        float2 G[4][4];
        // A = CRX(0,1)*(T0xT1), indices (q0=partner H, q1=m16 L)
        kron4(G, T0, T1); ctrlH_mul(G, R01);
        extractRow(G, 2*wid + lb[4], Aq[L]);
        // B = CRX(2,3)*CRX(1,2)|q1*(T2xT3), (q2=m8 H, q3=m4 L)
        kron4(G, T2, T3); tgtH_mul(G, R12c); ctrlH_mul(G, R23);
        extractRow(G, 2*lb[3] + lb[2], Bc[L]);
        // C = CRX(4,5)*CRX(3,4)|q3*(T4xT5), (q4=m2 H, q5=m1 L)
        kron4(G, T4, T5); tgtH_mul(G, R34c); ctrlH_mul(G, R45);
        extractRow(G, 2*lb[1] + lb[0], Cc[L]);

#pragma unroll
        for (int j = 0; j < 4; ++j) {   // down-ring: ctrl lb[j], tgt mask 2<<j
            float2 c2 = g_crx[L*12 + 6 + j]; int p = lb[j];
            dgc[L*4 + j] = p ? c2.x : 1.f;  dgs[L*4 + j] = p ? c2.y : 0.f;
        }
        // fused CRX(5,0)+CRX(1,0): both RX on q0 (warp bit), angles add per lane
        float2 a50 = g_crx[L*12+5], a10 = g_crx[L*12+10];
        float c50 = lb[0] ? a50.x : 1.f, s50 = lb[0] ? a50.y : 0.f;
        float c10 = lb[4] ? a10.x : 1.f, s10 = lb[4] ? a10.y : 0.f;
        c0c[L] = c50 * c10 - s50 * s10;
        c0s[L] = s50 * c10 + c50 * s10;
        float2 a05 = g_crx[L*12+11];
        c5c[L] = wid ? a05.x : 1.f;  c5s[L] = wid ? a05.y : 0.f;
    }

    // zi gather lanes + qubit-select predicates (epilogue uses tid<18 = warp 0)
    int srcZi = 26;
    if (lane == 7)  srcZi = 16;
    if (lane == 8)  srcZi = 24;
    if (lane == 9)  srcZi = 20;
    if (lane == 10) srcZi = 28;
    if (lane == 11) srcZi = 18;
    const int qsel = lane % 6;
    const bool q0b = qsel == 0, q1b = qsel == 1, q2b = qsel == 2, q3b = qsel == 3, q4b = qsel == 4;
#define SEL6(v) (q0b ? v[0] : q1b ? v[1] : q2b ? v[2] : q3b ? v[3] : q4b ? v[4] : v[5])

    float h[6] = {0.f, 0.f, 0.f, 0.f, 0.f, 0.f};
    const float*  angB = angles + (size_t)b * SEQ * 6;
    const float4* pkB  = g_pk   + (size_t)b * SEQ * 3;
    const float*  cwB  = g_cw   + (size_t)b * SEQ * 18;
    float*        outB = out    + (size_t)b * SEQ * 18;
    const float   Dme  = (tid < 18) ? Dv_in[tid] : 0.f;

    // preload t=0 inputs
    float4 f0 = __ldg(pkB + 0), f1 = __ldg(pkB + 1), f2 = __ldg(pkB + 2);
    float cwv = (tid < 18) ? __ldg(cwB + tid) : 0.f;
    float xme = (tid < 18) ? __ldg(angB + qsel) : 0.f;

#pragma unroll 1
    for (int t = 0; t < SEQ; ++t) {
        // ---- prefetch next step ----
        const int tn = (t + 1 < SEQ) ? t + 1 : t;
        float4 f0n = __ldg(pkB + tn*3 + 0), f1n = __ldg(pkB + tn*3 + 1), f2n = __ldg(pkB + tn*3 + 2);
        float cwn = (tid < 18) ? __ldg(cwB + tn*18 + tid) : 0.f;
        float xmn = (tid < 18) ? __ldg(angB + tn*6 + qsel) : 0.f;

        float dta[6] = {f0.x, f0.y, f0.z, f0.w, f1.x, f1.y};
        float xdt[6] = {f1.z, f1.w, f2.x, f2.y, f2.z, f2.w};

        // ---- QSVT phase + fold sincos ----
        float acc = Bq[0] * dta[0];
#pragma unroll
        for (int i = 1; i < 6; ++i) acc = fmaf(Bq[i], dta[i], acc);
        float cph, sph;
        __sincosf(acc, &sph, &cph);
        float c6[6], s6[6];
#pragma unroll
        for (int i = 0; i < 6; ++i) __sincosf(xdt[i], &s6[i], &c6[i]);

        // ---- initial RY(h) product state at sigma^{-4}(tid), times phase ----
        float hcv[6], hsv[6];
#pragma unroll
        for (int i = 0; i < 6; ++i) __sincosf(0.5f * h[i], &hsv[i], &hcv[i]);
        float pr = 1.f;
#pragma unroll
        for (int i = 0; i < 6; ++i)
            pr *= ((s4 >> (5 - i)) & 1) ? hsv[i] : hcv[i];
        float r = pr * cph, im = pr * sph;

        // ---- ansatz: 2 layers ----
#pragma unroll
        for (int L = 0; L < 2; ++L) {
            { // A block: exchange partner amp (buffer 2L)
                sX[2*L][tid] = r; sY[2*L][tid] = im;
                __syncthreads();
                float prr = sX[2*L][tid ^ 32], pii = sY[2*L][tid ^ 32];
                float s16r = SH(r, 16),  s16i = SH(im, 16);
                float p16r = SH(prr, 16), p16i = SH(pii, 16);
                const float* A = Aq[L];
                float nr = A[0]*r - A[1]*im + A[2]*s16r - A[3]*s16i
                         + A[4]*prr - A[5]*pii + A[6]*p16r - A[7]*p16i;
                float ni = A[0]*im + A[1]*r + A[2]*s16i + A[3]*s16r
                         + A[4]*pii + A[5]*prr + A[6]*p16i + A[7]*p16r;
                r = nr; im = ni;
            }
            { // B block (m8,m4)
                float ar = SH(r,4), ai = SH(im,4), br = SH(r,8), bi = SH(im,8);
                float cr = SH(r,12), ci = SH(im,12);
                const float* C = Bc[L];
                float nr = C[0]*r - C[1]*im + C[2]*ar - C[3]*ai + C[4]*br - C[5]*bi + C[6]*cr - C[7]*ci;
                float ni = C[0]*im + C[1]*r + C[2]*ai + C[3]*ar + C[4]*bi + C[5]*br + C[6]*ci + C[7]*cr;
                r = nr; im = ni;
            }
            { // C block (m2,m1)
                float ar = SH(r,1), ai = SH(im,1), br = SH(r,2), bi = SH(im,2);
                float cr = SH(r,3), ci = SH(im,3);
                const float* C = Cc[L];
                float nr = C[0]*r - C[1]*im + C[2]*ar - C[3]*ai + C[4]*br - C[5]*bi + C[6]*cr - C[7]*ci;
                float ni = C[0]*im + C[1]*r + C[2]*ai + C[3]*ar + C[4]*bi + C[5]*br + C[6]*ci + C[7]*cr;
                r = nr; im = ni;
            }
            // down-ring intra-warp CRXs: tgt masks 2,4,8,16
#pragma unroll
            for (int j = 0; j < 4; ++j) {
                int m = 2 << j;
                float cE = dgc[L*4 + j], sE = dgs[L*4 + j];
                float nr = cE*r + sE*SH(im, m);
                float ni = cE*im - sE*SH(r, m);
                r = nr; im = ni;
            }
            { // fused CRX(5,0)*CRX(1,0): RX on warp bit (buffer 2L+1)
                sX[2*L+1][tid] = r; sY[2*L+1][tid] = im;
                __syncthreads();
                float prr = sX[2*L+1][tid ^ 32], pii = sY[2*L+1][tid ^ 32];
                float nr = c0c[L]*r + c0s[L]*pii;
                float ni = c0c[L]*im - c0s[L]*prr;
                r = nr; im = ni;
            }
            { // CRX(0,5): ctrl warp bit, tgt m1
                float nr = c5c[L]*r + c5s[L]*SH(im, 1);
                float ni = c5c[L]*im - c5s[L]*SH(r, 1);
                r = nr; im = ni;
            }
        }

        // ---- measurements ----
        // amp exchange (buffer 4) for z0
        sX[4][tid] = r; sY[4][tid] = im;
        __syncthreads();
        float prr = sX[4][tid ^ 32], pii = sY[4][tid ^ 32];

        float w = r*r + im*im;
        float fq = w;
#pragma unroll
        for (int st = 0; st < 5; ++st) {
            int m = 16 >> st;
            float p = SH(fq, m);
            fq = (lane & m) ? (p - fq) : (fq + p);
        }

        float vr[5], vi[5];
#pragma unroll
        for (int i = 1; i <= 5; ++i) {
            int m = 1 << (5 - i);
            float rr = SH(r, m), ii = SH(im, m);
            float tr = r*rr + im*ii;
            float ti = r*ii - im*rr;
            int bit = (lane >> (5 - i)) & 1;
            vr[i-1] = bit ? 0.f : tr;
            vi[i-1] = bit ? 0.f : ti;
        }
        float zr0 = wid ? 0.f : (r*prr + im*pii);
        float zi0 = wid ? 0.f : (r*pii - im*prr);

        // packed reduction: 12 sums in-warp
        float P1, P2, P3, P4, P5, P6;
        { float a = vr[0] + SH(vr[0],16), bb = vi[0] + SH(vi[0],16); P1 = (lane&16) ? bb : a; }
        { float a = vr[1] + SH(vr[1],16), bb = vi[1] + SH(vi[1],16); P2 = (lane&16) ? bb : a; }
        { float a = vr[2] + SH(vr[2],16), bb = vi[2] + SH(vi[2],16); P3 = (lane&16) ? bb : a; }
        { float a = vr[3] + SH(vr[3],16), bb = vi[3] + SH(vi[3],16); P4 = (lane&16) ? bb : a; }
        { float a = vr[4] + SH(vr[4],16), bb = vi[4] + SH(vi[4],16); P5 = (lane&16) ? bb : a; }
        { float a = zr0   + SH(zr0,  16), bb = zi0   + SH(zi0,  16); P6 = (lane&16) ? bb : a; }
        float Q1, Q2, Q3;
        { float a = P1 + SH(P1,8), bb = P2 + SH(P2,8); Q1 = (lane&8) ? bb : a; }
        { float a = P3 + SH(P3,8), bb = P4 + SH(P4,8); Q2 = (lane&8) ? bb : a; }
        { float a = P5 + SH(P5,8), bb = P6 + SH(P6,8); Q3 = (lane&8) ? bb : a; }
        float R1, R2;
        { float a = Q1 + SH(Q1,4), bb = Q2 + SH(Q2,4); R1 = (lane&4) ? bb : a; }
        R2 = Q3 + SH(Q3,4);
        float Sv;
        { float a = R1 + SH(R1,2), bb = R2 + SH(R2,2); Sv = (lane&2) ? bb : a; }
        Sv += SH(Sv, 1);

        // cross-warp combine (buffer 5): Sv and fq
        sX[5][tid] = Sv; sY[5][tid] = fq;
        __syncthreads();
        float Svp = sX[5][tid ^ 32], fp = sY[5][tid ^ 32];
        float SvT = Sv + Svp;
        float fT  = fq + fp;
        float gv  = wid ? (fp - fq) : (fq - fp);   // warp0 sum - warp1 sum, identical both warps

        float Zt[6];
        Zt[0] = __shfl_sync(FULLM, gv, 0);
        Zt[1] = __shfl_sync(FULLM, fT, 16);
        Zt[2] = __shfl_sync(FULLM, fT, 8);
        Zt[3] = __shfl_sync(FULLM, fT, 4);
        Zt[4] = __shfl_sync(FULLM, fT, 2);
        Zt[5] = __shfl_sync(FULLM, fT, 1);

        float zrB[6];
        zrB[0] = __shfl_sync(FULLM, SvT, 10);
        zrB[1] = __shfl_sync(FULLM, SvT, 0);
        zrB[2] = __shfl_sync(FULLM, SvT, 8);
        zrB[3] = __shfl_sync(FULLM, SvT, 4);
        zrB[4] = __shfl_sync(FULLM, SvT, 12);
        zrB[5] = __shfl_sync(FULLM, SvT, 2);
        float giZ = __shfl_sync(FULLM, SvT, srcZi);

#pragma unroll
        for (int i = 0; i < 6; ++i)
            h[i] = c6[i] * Zt[i] - s6[i] * (2.f * zrB[i]);

        float csel = SEL6(c6), ssel = SEL6(s6), zrsel = SEL6(zrB),
              ztsel = SEL6(Zt), hsel = SEL6(h);
        float mval = (tid < 6)  ? fmaf(csel, 2.f * zrsel, ssel * ztsel)
                   : (tid < 12) ? 2.f * giZ
                                : hsel;
        if (tid < 18)
            outB[t * 18 + tid] = cwv * mval + Dme * xme;

        f0 = f0n; f1 = f1n; f2 = f2n; cwv = cwn; xme = xmn;
    }
#undef SEL6
}

// ---------------- launch ----------------
extern "C" void kernel_launch(void* const* d_in, const int* in_sizes, int n_in,
                              void* d_out, int out_size) {
    const float* angles = (const float*)d_in[0];
    const float* Wx     = (const float*)d_in[1];
    const float* Wdt    = (const float*)d_in[2];
    const float* bdt    = (const float*)d_in[3];
    const float* pc     = (const float*)d_in[4];
    const float* qp     = (const float*)d_in[5];
    const float* cp     = (const float*)d_in[6];
    const float* D      = (const float*)d_in[7];
    const float* Wc     = (const float*)d_in[8];

    prep_kernel <<<(BATCH * SEQ + 255) / 256, 256>>>(angles, Wx, Wdt, bdt, Wc);
    prep2_kernel<<<1, 64>>>(pc, qp, cp);
    sim_kernel  <<<BATCH, 64>>>(angles, D, (float*)d_out);
}

// round 14
// speedup vs baseline: 1.0421x; 1.0421x over previous
#include <cuda_runtime.h>
#include <cstdint>

#define NQ     6
#define BATCH  256
#define SEQ    512
#define FULLM  0xffffffffu
#define PI_F   3.14159265358979323846f
#define SH(v,m) __shfl_xor_sync(FULLM, (v), (m))

// ---------------- scratch ----------------
__device__ float4 g_pk [BATCH * SEQ * 2];   // [dta0..3][dta4,dta5,-,-]
__device__ float4 g_cs6[BATCH * SEQ * 3];   // fold sincos (c,s) x6
__device__ float  g_cw [BATCH * SEQ * 18];
__device__ float  g_tf [24];
__device__ float2 g_fa [12];   // trio alpha (L*6+i)
__device__ float2 g_fb [12];   // trio beta
__device__ float2 g_crx[24];   // (cos,sin) half-angle: L*12 + [0..5 up][6..11 down]

// ---------------- prep 1 ----------------
__global__ void prep_kernel(const float* __restrict__ angles,
                            const float* __restrict__ Wx,
                            const float* __restrict__ Wdt,
                            const float* __restrict__ bdt,
                            const float* __restrict__ Wc) {
    int idx = blockIdx.x * blockDim.x + threadIdx.x;
    if (idx >= BATCH * SEQ) return;
    float a[6];
#pragma unroll
    for (int k = 0; k < 6; ++k) a[k] = angles[idx * 6 + k];
    float dtr[3];
#pragma unroll
    for (int r = 0; r < 3; ++r) {
        float s = 0.f;
#pragma unroll
        for (int k = 0; k < 6; ++k) s += a[k] * Wx[r * 6 + k];
        dtr[r] = s;
    }
    float C[6];
#pragma unroll
    for (int j = 0; j < 6; ++j) {
        float s = 0.f;
#pragma unroll
        for (int k = 0; k < 6; ++k) s += a[k] * Wx[(9 + j) * 6 + k];
        C[j] = s;
    }
    float dta[6];
#pragma unroll
    for (int i = 0; i < 6; ++i) {
        float v = bdt[i];
#pragma unroll
        for (int r = 0; r < 3; ++r) v += dtr[r] * Wdt[i * 3 + r];
        float sp = (v > 20.f) ? v : log1pf(expf(v));
        dta[i] = tanhf(sp) * PI_F;
    }
    g_pk[idx * 2 + 0] = make_float4(dta[0], dta[1], dta[2], dta[3]);
    g_pk[idx * 2 + 1] = make_float4(dta[4], dta[5], 0.f, 0.f);
    float c6[6], s6[6];
#pragma unroll
    for (int i = 0; i < 6; ++i) __sincosf(a[i] * dta[i], &s6[i], &c6[i]);
    g_cs6[idx * 3 + 0] = make_float4(c6[0], s6[0], c6[1], s6[1]);
    g_cs6[idx * 3 + 1] = make_float4(c6[2], s6[2], c6[3], s6[3]);
    g_cs6[idx * 3 + 2] = make_float4(c6[4], s6[4], c6[5], s6[5]);
#pragma unroll
    for (int j = 0; j < 18; ++j) {
        float s = 0.f;
#pragma unroll
        for (int k = 0; k < 6; ++k) s += C[k] * Wc[j * 6 + k];
        g_cw[idx * 18 + j] = s;
    }
}

// ---------------- prep 2 ----------------
__global__ void prep2_kernel(const float* __restrict__ pc,
                             const float* __restrict__ qp,
                             const float* __restrict__ cp) {
    int t = threadIdx.x;
    if (t < 24) {
        int d = t / 6, i = t % 6;
        g_tf[t] = pc[d] * PI_F * ((d < 3) ? qp[d * 6 + i] : 1.0f);
    }
    if (t < 24) {
        int L = t / 12, k = t % 12;
        float ang = (k < 6) ? cp[L * 30 + 18 + k] : cp[L * 30 + 24 + (k - 6)];
        float th = 0.5f * ang;
        g_crx[t] = make_float2(cosf(th), sinf(th));
    }
    if (t < 12) {   // U = RZ(c)*RY(b)*RX(a), half angles
        int L = t / 6, i = t % 6, base = L * 30 + i * 3;
        float cx = cosf(0.5f * cp[base]),     sx = sinf(0.5f * cp[base]);
        float cy = cosf(0.5f * cp[base + 1]), sy = sinf(0.5f * cp[base + 1]);
        float cz = cosf(0.5f * cp[base + 2]), sz = sinf(0.5f * cp[base + 2]);
        float M00r = cy * cx, M00i = sy * sx;
        float M10r = sy * cx, M10i = -cy * sx;
        g_fa[t] = make_float2(cz * M00r + sz * M00i, cz * M00i - sz * M00r);
        g_fb[t] = make_float2(cz * M10r - sz * M10i, cz * M10i + sz * M10r);
    }
}

// ---------------- complex / matrix helpers (prologue only) ----------------
__device__ __forceinline__ float2 cmul2(float2 a, float2 b) {
    return make_float2(a.x*b.x - a.y*b.y, a.x*b.y + a.y*b.x);
}
__device__ __forceinline__ float2 cadd2(float2 a, float2 b) {
    return make_float2(a.x + b.x, a.y + b.y);
}
struct M2 { float2 m[2][2]; };
__device__ __forceinline__ M2 mkT(float2 al, float2 be) {
    M2 t;
    t.m[0][0] = al; t.m[0][1] = make_float2(-be.x, be.y);
    t.m[1][0] = be; t.m[1][1] = make_float2(al.x, -al.y);
    return t;
}
__device__ __forceinline__ M2 mkRX(float c, float s) {
    M2 t;
    t.m[0][0] = make_float2(c, 0.f); t.m[0][1] = make_float2(0.f, -s);
    t.m[1][0] = make_float2(0.f, -s); t.m[1][1] = make_float2(c, 0.f);
    return t;
}
__device__ __forceinline__ void kron4(float2 G[4][4], const M2& A, const M2& B) {
#pragma unroll
    for (int i = 0; i < 2; ++i)
#pragma unroll
    for (int j = 0; j < 2; ++j)
#pragma unroll
    for (int k = 0; k < 2; ++k)
#pragma unroll
    for (int l = 0; l < 2; ++l)
        G[2*i + k][2*j + l] = cmul2(A.m[i][j], B.m[k][l]);
}
// left-multiply by ctrl-on-HIGH gate (rows 2,3 mixed by R)
__device__ __forceinline__ void ctrlH_mul(float2 G[4][4], const M2& R) {
#pragma unroll
    for (int c = 0; c < 4; ++c) {
        float2 t2 = G[2][c], t3 = G[3][c];
        G[2][c] = cadd2(cmul2(R.m[0][0], t2), cmul2(R.m[0][1], t3));
        G[3][c] = cadd2(cmul2(R.m[1][0], t2), cmul2(R.m[1][1], t3));
    }
}
// left-multiply by R acting on HIGH qubit: mixes rows (0,2) and (1,3)
__device__ __forceinline__ void tgtH_mul(float2 G[4][4], const M2& R) {
#pragma unroll
    for (int c = 0; c < 4; ++c) {
#pragma unroll
        for (int aL = 0; aL < 2; ++aL) {
            float2 t0 = G[aL][c], t1 = G[2 + aL][c];
            G[aL][c]     = cadd2(cmul2(R.m[0][0], t0), cmul2(R.m[0][1], t1));
            G[2 + aL][c] = cadd2(cmul2(R.m[1][0], t0), cmul2(R.m[1][1], t1));
        }
    }
}
// extract A-type coeffs (H = reg bit, L = lane bit bL): rows d0, d0^2
__device__ __forceinline__ void extractA(const float2 G[4][4], int bL, float* A, float* B) {
    float2 a0 = bL ? G[1][1] : G[0][0], a1 = bL ? G[1][0] : G[0][1];
    float2 a2 = bL ? G[1][3] : G[0][2], a3 = bL ? G[1][2] : G[0][3];
    A[0]=a0.x; A[1]=a0.y; A[2]=a1.x; A[3]=a1.y; A[4]=a2.x; A[5]=a2.y; A[6]=a3.x; A[7]=a3.y;
    float2 b0 = bL ? G[3][1] : G[2][0], b1 = bL ? G[3][0] : G[2][1];
    float2 b2 = bL ? G[3][3] : G[2][2], b3 = bL ? G[3][2] : G[2][3];
    B[0]=b0.x; B[1]=b0.y; B[2]=b1.x; B[3]=b1.y; B[4]=b2.x; B[5]=b2.y; B[6]=b3.x; B[7]=b3.y;
}
// extract pair coeffs: d = 2*bH + bL; c_j = G[d][d^j]
__device__ __forceinline__ void extractP(const float2 G[4][4], int bH, int bL, float* C) {
    int d = 2*bH + bL;
#pragma unroll
    for (int j = 0; j < 4; ++j) {
        float2 c = (d == 0) ? G[0][j] : (d == 1) ? G[1][1^j] : (d == 2) ? G[2][2^j] : G[3][3^j];
        C[2*j] = c.x; C[2*j + 1] = c.y;
    }
}

// ---------------- runtime gate primitives ----------------
__device__ __forceinline__ void applyA(float& r0, float& i0, float& r1, float& i1,
                                       int mL, const float* A, const float* B) {
    float p0 = SH(r0, mL), q0 = SH(i0, mL), p1 = SH(r1, mL), q1 = SH(i1, mL);
    float nr0 = A[0]*r0 - A[1]*i0 + A[2]*p0 - A[3]*q0 + A[4]*r1 - A[5]*i1 + A[6]*p1 - A[7]*q1;
    float ni0 = A[0]*i0 + A[1]*r0 + A[2]*q0 + A[3]*p0 + A[4]*i1 + A[5]*r1 + A[6]*q1 + A[7]*p1;
    float nr1 = B[0]*r0 - B[1]*i0 + B[2]*p0 - B[3]*q0 + B[4]*r1 - B[5]*i1 + B[6]*p1 - B[7]*q1;
    float ni1 = B[0]*i0 + B[1]*r0 + B[2]*q0 + B[3]*p0 + B[4]*i1 + B[5]*r1 + B[6]*q1 + B[7]*p1;
    r0 = nr0; i0 = ni0; r1 = nr1; i1 = ni1;
}
__device__ __forceinline__ void applyP(float& r0, float& i0, float& r1, float& i1,
                                       int mH, int mL, const float* C) {
    const int mHL = mH | mL;
    float Ar0 = SH(r0, mL),  Ai0 = SH(i0, mL),  Ar1 = SH(r1, mL),  Ai1 = SH(i1, mL);
    float Br0 = SH(r0, mH),  Bi0 = SH(i0, mH),  Br1 = SH(r1, mH),  Bi1 = SH(i1, mH);
    float Cr0 = SH(r0, mHL), Ci0 = SH(i0, mHL), Cr1 = SH(r1, mHL), Ci1 = SH(i1, mHL);
    float nr0 = C[0]*r0 - C[1]*i0 + C[2]*Ar0 - C[3]*Ai0 + C[4]*Br0 - C[5]*Bi0 + C[6]*Cr0 - C[7]*Ci0;
    float ni0 = C[0]*i0 + C[1]*r0 + C[2]*Ai0 + C[3]*Ar0 + C[4]*Bi0 + C[5]*Br0 + C[6]*Ci0 + C[7]*Cr0;
    float nr1 = C[0]*r1 - C[1]*i1 + C[2]*Ar1 - C[3]*Ai1 + C[4]*Br1 - C[5]*Bi1 + C[6]*Cr1 - C[7]*Ci1;
    float ni1 = C[0]*i1 + C[1]*r1 + C[2]*Ai1 + C[3]*Ar1 + C[4]*Bi1 + C[5]*Br1 + C[6]*Ci1 + C[7]*Cr1;
    r0 = nr0; i0 = ni0; r1 = nr1; i1 = ni1;
}
__device__ __forceinline__ void crx_gen(float& r0, float& i0, float& r1, float& i1,
                                        int m, float cE, float sE) {
    float pr0 = SH(r0, m), pi0 = SH(i0, m), pr1 = SH(r1, m), pi1 = SH(i1, m);
    float nr0 = cE*r0 + sE*pi0, ni0 = cE*i0 - sE*pr0;
    float nr1 = cE*r1 + sE*pi1, ni1 = cE*i1 - sE*pr1;
    r0 = nr0; i0 = ni0; r1 = nr1; i1 = ni1;
}
__device__ __forceinline__ void crx_treg(float& r0, float& i0, float& r1, float& i1,
                                         float cE, float sE) {
    float nr0 = cE*r0 + sE*i1, ni0 = cE*i0 - sE*r1;
    float nr1 = cE*r1 + sE*i0, ni1 = cE*i1 - sE*r0;
    r0 = nr0; i0 = ni0; r1 = nr1; i1 = ni1;
}
__device__ __forceinline__ void crx_cb5(float& r1, float& i1, int m, float c, float s) {
    float p = SH(r1, m), q = SH(i1, m);
    float nr1 = fmaf(s, q, c * r1);
    float ni1 = fmaf(-s, p, c * i1);
    r1 = nr1; i1 = ni1;
}

// ---------------- main sim: one warp per chain ----------------
__global__ void __launch_bounds__(32, 1)
sim_kernel(const float* __restrict__ angles,
           const float* __restrict__ Dv_in,
           float* __restrict__ out) {
    const int b    = blockIdx.x;
    const int lane = threadIdx.x;

    // ---- composed QSVT: sigma^4 source indices + per-amp phase coefficients B ----
    int fwd[64];
    for (int s = 0; s < 64; ++s) {
        int q[6];
#pragma unroll
        for (int i = 0; i < 6; ++i) q[i] = (s >> (5 - i)) & 1;
        q[1]^=q[0]; q[2]^=q[1]; q[3]^=q[2]; q[4]^=q[3]; q[5]^=q[4];
        q[0]^=q[5]; q[4]^=q[5]; q[3]^=q[4]; q[2]^=q[3]; q[1]^=q[2]; q[0]^=q[1];
        int tt = 0;
#pragma unroll
        for (int i = 0; i < 6; ++i) tt |= q[i] << (5 - i);
        fwd[s] = tt;
    }
    int inv[64];
    for (int s = 0; s < 64; ++s) inv[fwd[s]] = s;

    float B0[6] = {0,0,0,0,0,0}, B1[6] = {0,0,0,0,0,0};
    int u0 = lane, u1 = lane + 32;
    for (int k = 1; k <= 4; ++k) {
        u0 = inv[u0]; u1 = inv[u1];
        int d = 4 - k;
#pragma unroll
        for (int i = 0; i < 6; ++i) {
            float c = 0.5f * g_tf[d * 6 + i];
            B0[i] += ((u0 >> (5 - i)) & 1) ? c : -c;
            B1[i] += ((u1 >> (5 - i)) & 1) ? c : -c;
        }
    }
    const int s40 = u0, s41 = u1;

    int lbit[5];
#pragma unroll
    for (int bp = 0; bp < 5; ++bp) lbit[bp] = (lane >> bp) & 1;
    // qubit bits: q1=lbit[4], q2=lbit[3], q3=lbit[2], q4=lbit[1], q5=lbit[0]

    // ---- build per-lane block-gate coefficients (one-time) ----
    float Aa[2][8], Ab[2][8], Bc[2][8], Cc[2][8];
    float utc[2], uts[2], dtc[2], dts[2], C5c[2], C5s[2];
    float dgc[8], dgs[8];
#pragma unroll
    for (int L = 0; L < 2; ++L) {
        M2 T0 = mkT(g_fa[L*6+0], g_fb[L*6+0]);
        M2 T1 = mkT(g_fa[L*6+1], g_fb[L*6+1]);
        M2 T2 = mkT(g_fa[L*6+2], g_fb[L*6+2]);
        M2 T3 = mkT(g_fa[L*6+3], g_fb[L*6+3]);
        M2 T4 = mkT(g_fa[L*6+4], g_fb[L*6+4]);
        M2 T5 = mkT(g_fa[L*6+5], g_fb[L*6+5]);
        float2 cs;
        cs = g_crx[L*12+0];  M2 R01 = mkRX(cs.x, cs.y);
        cs = g_crx[L*12+1];  M2 R12c = mkRX(lbit[4] ? cs.x : 1.f, lbit[4] ? cs.y : 0.f);
        cs = g_crx[L*12+2];  M2 R23 = mkRX(cs.x, cs.y);
        cs = g_crx[L*12+3];  M2 R34c = mkRX(lbit[2] ? cs.x : 1.f, lbit[2] ? cs.y : 0.f);
        cs = g_crx[L*12+4];  M2 R45 = mkRX(cs.x, cs.y);
        cs = g_crx[L*12+5];  { int p = lbit[0]; utc[L] = p ? cs.x : 1.f; uts[L] = p ? cs.y : 0.f; }
#pragma unroll
        for (int j = 0; j < 4; ++j) {   // down-ring generals: ctrl bp j, tgt mask 2<<j
            float2 c2 = g_crx[L*12 + 6 + j]; int p = lbit[j];
            dgc[L*4 + j] = p ? c2.x : 1.f;  dgs[L*4 + j] = p ? c2.y : 0.f;
        }
        cs = g_crx[L*12+10]; { int p = lbit[4]; dtc[L] = p ? cs.x : 1.f; dts[L] = p ? cs.y : 0.f; }
        cs = g_crx[L*12+11]; C5c[L] = cs.x; C5s[L] = cs.y;

        float2 G[4][4];
        // A = CRX(0,1) * (T0 x T1) on (q0=reg H, q1=m16 L)
        kron4(G, T0, T1); ctrlH_mul(G, R01);
        extractA(G, lbit[4], Aa[L], Ab[L]);
        // B = CRX(2,3) * CRX(1,2)|q1 * (T2 x T3) on (q2=m8 H, q3=m4 L)
        kron4(G, T2, T3); tgtH_mul(G, R12c); ctrlH_mul(G, R23);
        extractP(G, lbit[3], lbit[2], Bc[L]);
        // C = CRX(4,5) * CRX(3,4)|q3 * (T4 x T5) on (q4=m2 H, q5=m1 L)
        kron4(G, T4, T5); tgtH_mul(G, R34c); ctrlH_mul(G, R45);
        extractP(G, lbit[1], lbit[0], Cc[L]);
    }

    // zi gather lanes + qubit-select predicates
    int srcZi = 26;
    if (lane == 7)  srcZi = 16;
    if (lane == 8)  srcZi = 24;
    if (lane == 9)  srcZi = 20;
    if (lane == 10) srcZi = 28;
    if (lane == 11) srcZi = 18;
    const int qsel = lane % 6;
    const bool q0 = qsel == 0, q1 = qsel == 1, q2 = qsel == 2, q3 = qsel == 3, q4 = qsel == 4;
#define SEL6(v) (q0 ? v[0] : q1 ? v[1] : q2 ? v[2] : q3 ? v[3] : q4 ? v[4] : v[5])

    float h[6] = {0.f, 0.f, 0.f, 0.f, 0.f, 0.f};
    const float*  angB = angles + (size_t)b * SEQ * 6;
    const float4* pkB  = g_pk   + (size_t)b * SEQ * 2;
    const float4* csB  = g_cs6  + (size_t)b * SEQ * 3;
    const float*  cwB  = g_cw   + (size_t)b * SEQ * 18;
    float*        outB = out    + (size_t)b * SEQ * 18;
    const float   Dme  = (lane < 18) ? Dv_in[lane] : 0.f;

    // preload t=0 inputs
    float4 f0 = __ldg(pkB + 0), f1 = __ldg(pkB + 1);
    float4 e0 = __ldg(csB + 0), e1 = __ldg(csB + 1), e2 = __ldg(csB + 2);
    float cwv = (lane < 18) ? __ldg(cwB + lane) : 0.f;
    float xme = (lane < 18) ? __ldg(angB + qsel) : 0.f;

#pragma unroll 1
    for (int t = 0; t < SEQ; ++t) {
        // ---- prefetch next step's inputs ----
        const int tn = (t + 1 < SEQ) ? t + 1 : t;
        float4 f0n = __ldg(pkB + tn*2 + 0), f1n = __ldg(pkB + tn*2 + 1);
        float4 e0n = __ldg(csB + tn*3 + 0), e1n = __ldg(csB + tn*3 + 1), e2n = __ldg(csB + tn*3 + 2);
        float cwn = (lane < 18) ? __ldg(cwB + tn*18 + lane) : 0.f;
        float xmn = (lane < 18) ? __ldg(angB + tn*6 + qsel) : 0.f;

        float dta[6] = {f0.x, f0.y, f0.z, f0.w, f1.x, f1.y};
        float c6[6] = {e0.x, e0.z, e1.x, e1.z, e2.x, e2.z};
        float s6[6] = {e0.y, e0.w, e1.y, e1.w, e2.y, e2.w};

        // ---- h-independent math: QSVT phase ----
        float acc0 = B0[0] * dta[0], acc1 = B1[0] * dta[0];
#pragma unroll
        for (int i = 1; i < 6; ++i) {
            acc0 = fmaf(B0[i], dta[i], acc0);
            acc1 = fmaf(B1[i], dta[i], acc1);
        }
        float c0, s0, c1, s1;
        __sincosf(acc0, &s0, &c0);
        __sincosf(acc1, &s1, &c1);

        // ---- initial RY(h) product state at sigma^{-4} indices, times QSVT phase ----
        float hcv[6], hsv[6];
#pragma unroll
        for (int i = 0; i < 6; ++i) __sincosf(0.5f * h[i], &hsv[i], &hcv[i]);
        float pr0 = 1.f, pr1 = 1.f;
#pragma unroll
        for (int i = 0; i < 6; ++i) {
            pr0 *= ((s40 >> (5 - i)) & 1) ? hsv[i] : hcv[i];
            pr1 *= ((s41 >> (5 - i)) & 1) ? hsv[i] : hcv[i];
        }
        float r0 = pr0 * c0, i0 = pr0 * s0;
        float r1 = pr1 * c1, i1 = pr1 * s1;

        // ---- ansatz: 2 layers: A, B, C fused blocks + scalar down-ring ----
#pragma unroll
        for (int L = 0; L < 2; ++L) {
            applyA(r0, i0, r1, i1, 16, Aa[L], Ab[L]);      // CRX01 * T0xT1
            applyP(r0, i0, r1, i1, 8, 4, Bc[L]);           // CRX23*CRX12*T2xT3
            applyP(r0, i0, r1, i1, 2, 1, Cc[L]);           // CRX45*CRX34*T4xT5
            crx_treg(r0, i0, r1, i1, utc[L], uts[L]);      // CRX(5,0)
            crx_gen(r0, i0, r1, i1, 2,  dgc[L*4+0], dgs[L*4+0]);  // CRX(5,4)
            crx_gen(r0, i0, r1, i1, 4,  dgc[L*4+1], dgs[L*4+1]);  // CRX(4,3)
            crx_gen(r0, i0, r1, i1, 8,  dgc[L*4+2], dgs[L*4+2]);  // CRX(3,2)
            crx_gen(r0, i0, r1, i1, 16, dgc[L*4+3], dgs[L*4+3]);  // CRX(2,1)
            crx_treg(r0, i0, r1, i1, dtc[L], dts[L]);      // CRX(1,0)
            crx_cb5(r1, i1, 1, C5c[L], C5s[L]);            // CRX(0,5)
        }

        // ---- measurements ----
        float w0 = r0*r0 + i0*i0;
        float w1 = r1*r1 + i1*i1;
        float ws = w0 + w1, wd = w0 - w1;
        float f = ws;
#pragma unroll
        for (int st = 0; st < 5; ++st) {
            int m = 16 >> st;
            float p = SH(f, m);
            f = (lane & m) ? (p - f) : (f + p);
        }

        float vr[5], vi[5];
#pragma unroll
        for (int i = 1; i <= 5; ++i) {
            int m = 1 << (5 - i);
            float pr0s = SH(r0, m), pi0s = SH(i0, m), pr1s = SH(r1, m), pi1s = SH(i1, m);
            float tr = r0*pr0s + i0*pi0s + r1*pr1s + i1*pi1s;
            float ti = r0*pi0s - i0*pr0s + r1*pi1s - i1*pr1s;
            int bit = (lane >> (5 - i)) & 1;
            vr[i-1] = bit ? 0.f : tr;
            vi[i-1] = bit ? 0.f : ti;
        }
        float zr0 = r0*r1 + i0*i1;
        float zi0 = r0*i1 - i0*r1;

        // packed reduction: 12 pair sums + wd total in one tree
        float P1, P2, P3, P4, P5, P6, P7;
        { float a = vr[0] + SH(vr[0],16), bb = vi[0] + SH(vi[0],16); P1 = (lane&16) ? bb : a; }
        { float a = vr[1] + SH(vr[1],16), bb = vi[1] + SH(vi[1],16); P2 = (lane&16) ? bb : a; }
        { float a = vr[2] + SH(vr[2],16), bb = vi[2] + SH(vi[2],16); P3 = (lane&16) ? bb : a; }
        { float a = vr[3] + SH(vr[3],16), bb = vi[3] + SH(vi[3],16); P4 = (lane&16) ? bb : a; }
        { float a = vr[4] + SH(vr[4],16), bb = vi[4] + SH(vi[4],16); P5 = (lane&16) ? bb : a; }
        { float a = zr0   + SH(zr0,  16), bb = zi0   + SH(zi0,  16); P6 = (lane&16) ? bb : a; }
        P7 = wd + SH(wd, 16);
        float Q1, Q2, Q3, Q4;
        { float a = P1 + SH(P1,8), bb = P2 + SH(P2,8); Q1 = (lane&8) ? bb : a; }
        { float a = P3 + SH(P3,8), bb = P4 + SH(P4,8); Q2 = (lane&8) ? bb : a; }
        { float a = P5 + SH(P5,8), bb = P6 + SH(P6,8); Q3 = (lane&8) ? bb : a; }
        Q4 = P7 + SH(P7, 8);
        float R1, R2;
        { float a = Q1 + SH(Q1,4), bb = Q2 + SH(Q2,4); R1 = (lane&4) ? bb : a; }
        { float a = Q3 + SH(Q3,4), bb = Q4 + SH(Q4,4); R2 = (lane&4) ? bb : a; }
        float Sv;
        { float a = R1 + SH(R1,2), bb = R2 + SH(R2,2); Sv = (lane&2) ? bb : a; }
        Sv += SH(Sv, 1);
        // lane map: zr:{q0:10,q1:0,q2:8,q3:4,q4:12,q5:2}, zi=+16, wd total at lane 6
        float Zt[6];
        Zt[0] = __shfl_sync(FULLM, Sv, 6);
        Zt[1] = __shfl_sync(FULLM, f, 16);
        Zt[2] = __shfl_sync(FULLM, f, 8);
        Zt[3] = __shfl_sync(FULLM, f, 4);
        Zt[4] = __shfl_sync(FULLM, f, 2);
        Zt[5] = __shfl_sync(FULLM, f, 1);
        float zrB[6];
        zrB[0] = __shfl_sync(FULLM, Sv, 10);
        zrB[1] = __shfl_sync(FULLM, Sv, 0);
        zrB[2] = __shfl_sync(FULLM, Sv, 8);
        zrB[3] = __shfl_sync(FULLM, Sv, 4);
        zrB[4] = __shfl_sync(FULLM, Sv, 12);
        zrB[5] = __shfl_sync(FULLM, Sv, 2);
        float giZ = __shfl_sync(FULLM, Sv, srcZi);

#pragma unroll
        for (int i = 0; i < 6; ++i)
            h[i] = c6[i] * Zt[i] - s6[i] * (2.f * zrB[i]);

        float csel = SEL6(c6), ssel = SEL6(s6), zrsel = SEL6(zrB),
              ztsel = SEL6(Zt), hsel = SEL6(h);
        float mval = (lane < 6)  ? fmaf(csel, 2.f * zrsel, ssel * ztsel)
                   : (lane < 12) ? 2.f * giZ
                                 : hsel;
        if (lane < 18)
            outB[t * 18 + lane] = cwv * mval + Dme * xme;

        // rotate prefetched inputs in
        f0 = f0n; f1 = f1n; e0 = e0n; e1 = e1n; e2 = e2n; cwv = cwn; xme = xmn;
    }
#undef SEL6
}

// ---------------- launch ----------------
extern "C" void kernel_launch(void* const* d_in, const int* in_sizes, int n_in,
                              void* d_out, int out_size) {
    const float* angles = (const float*)d_in[0];
    const float* Wx     = (const float*)d_in[1];
    const float* Wdt    = (const float*)d_in[2];
    const float* bdt    = (const float*)d_in[3];
    const float* pc     = (const float*)d_in[4];
    const float* qp     = (const float*)d_in[5];
    const float* cp     = (const float*)d_in[6];
    const float* D      = (const float*)d_in[7];
    const float* Wc     = (const float*)d_in[8];

    prep_kernel <<<(BATCH * SEQ + 255) / 256, 256>>>(angles, Wx, Wdt, bdt, Wc);
    prep2_kernel<<<1, 64>>>(pc, qp, cp);
    sim_kernel  <<<BATCH, 32>>>(angles, D, (float*)d_out);
}

// round 15
// speedup vs baseline: 1.2515x; 1.2009x over previous
#include <cuda_runtime.h>
#include <cstdint>

#define NQ     6
#define BATCH  256
#define SEQ    512
#define FULLM  0xffffffffu
#define PI_F   3.14159265358979323846f
#define SH(v,m) __shfl_xor_sync(FULLM, (v), (m))

// ---------------- scratch ----------------
__device__ float4 g_pk [BATCH * SEQ * 2];   // [dta0..3][dta4,dta5,-,-]
__device__ float2 g_cs2[BATCH * SEQ * 6];   // fold sincos (c,s) per qubit
__device__ float  g_cw [BATCH * SEQ * 18];
__device__ float  g_tf [24];
__device__ float2 g_fa [12];   // trio alpha (L*6+i)
__device__ float2 g_fb [12];   // trio beta
__device__ float2 g_crx[24];   // (cos,sin) half-angle: L*12 + [0..5 up][6..11 down]

// ---------------- prep 1 ----------------
__global__ void prep_kernel(const float* __restrict__ angles,
                            const float* __restrict__ Wx,
                            const float* __restrict__ Wdt,
                            const float* __restrict__ bdt,
                            const float* __restrict__ Wc) {
    int idx = blockIdx.x * blockDim.x + threadIdx.x;
    if (idx >= BATCH * SEQ) return;
    float a[6];
#pragma unroll
    for (int k = 0; k < 6; ++k) a[k] = angles[idx * 6 + k];
    float dtr[3];
#pragma unroll
    for (int r = 0; r < 3; ++r) {
        float s = 0.f;
#pragma unroll
        for (int k = 0; k < 6; ++k) s += a[k] * Wx[r * 6 + k];
        dtr[r] = s;
    }
    float C[6];
#pragma unroll
    for (int j = 0; j < 6; ++j) {
        float s = 0.f;
#pragma unroll
        for (int k = 0; k < 6; ++k) s += a[k] * Wx[(9 + j) * 6 + k];
        C[j] = s;
    }
    float dta[6];
#pragma unroll
    for (int i = 0; i < 6; ++i) {
        float v = bdt[i];
#pragma unroll
        for (int r = 0; r < 3; ++r) v += dtr[r] * Wdt[i * 3 + r];
        float sp = (v > 20.f) ? v : log1pf(expf(v));
        dta[i] = tanhf(sp) * PI_F;
    }
    g_pk[idx * 2 + 0] = make_float4(dta[0], dta[1], dta[2], dta[3]);
    g_pk[idx * 2 + 1] = make_float4(dta[4], dta[5], 0.f, 0.f);
#pragma unroll
    for (int i = 0; i < 6; ++i) {
        float cv, sv;
        __sincosf(a[i] * dta[i], &sv, &cv);
        g_cs2[idx * 6 + i] = make_float2(cv, sv);
    }
#pragma unroll
    for (int j = 0; j < 18; ++j) {
        float s = 0.f;
#pragma unroll
        for (int k = 0; k < 6; ++k) s += C[k] * Wc[j * 6 + k];
        g_cw[idx * 18 + j] = s;
    }
}

// ---------------- prep 2 ----------------
__global__ void prep2_kernel(const float* __restrict__ pc,
                             const float* __restrict__ qp,
                             const float* __restrict__ cp) {
    int t = threadIdx.x;
    if (t < 24) {
        int d = t / 6, i = t % 6;
        g_tf[t] = pc[d] * PI_F * ((d < 3) ? qp[d * 6 + i] : 1.0f);
    }
    if (t < 24) {
        int L = t / 12, k = t % 12;
        float ang = (k < 6) ? cp[L * 30 + 18 + k] : cp[L * 30 + 24 + (k - 6)];
        float th = 0.5f * ang;
        g_crx[t] = make_float2(cosf(th), sinf(th));
    }
    if (t < 12) {   // U = RZ(c)*RY(b)*RX(a), half angles
        int L = t / 6, i = t % 6, base = L * 30 + i * 3;
        float cx = cosf(0.5f * cp[base]),     sx = sinf(0.5f * cp[base]);
        float cy = cosf(0.5f * cp[base + 1]), sy = sinf(0.5f * cp[base + 1]);
        float cz = cosf(0.5f * cp[base + 2]), sz = sinf(0.5f * cp[base + 2]);
        float M00r = cy * cx, M00i = sy * sx;
        float M10r = sy * cx, M10i = -cy * sx;
        g_fa[t] = make_float2(cz * M00r + sz * M00i, cz * M00i - sz * M00r);
        g_fb[t] = make_float2(cz * M10r - sz * M10i, cz * M10i + sz * M10r);
    }
}

// ---------------- complex / matrix helpers (prologue only) ----------------
__device__ __forceinline__ float2 cmul2(float2 a, float2 b) {
    return make_float2(a.x*b.x - a.y*b.y, a.x*b.y + a.y*b.x);
}
__device__ __forceinline__ float2 cadd2(float2 a, float2 b) {
    return make_float2(a.x + b.x, a.y + b.y);
}
struct M2 { float2 m[2][2]; };
__device__ __forceinline__ M2 mkT(float2 al, float2 be) {
    M2 t;
    t.m[0][0] = al; t.m[0][1] = make_float2(-be.x, be.y);
    t.m[1][0] = be; t.m[1][1] = make_float2(al.x, -al.y);
    return t;
}
__device__ __forceinline__ M2 mkRX(float c, float s) {
    M2 t;
    t.m[0][0] = make_float2(c, 0.f); t.m[0][1] = make_float2(0.f, -s);
    t.m[1][0] = make_float2(0.f, -s); t.m[1][1] = make_float2(c, 0.f);
    return t;
}
__device__ __forceinline__ void kron4(float2 G[4][4], const M2& A, const M2& B) {
#pragma unroll
    for (int i = 0; i < 2; ++i)
#pragma unroll
    for (int j = 0; j < 2; ++j)
#pragma unroll
    for (int k = 0; k < 2; ++k)
#pragma unroll
    for (int l = 0; l < 2; ++l)
        G[2*i + k][2*j + l] = cmul2(A.m[i][j], B.m[k][l]);
}
__device__ __forceinline__ void ctrlH_mul(float2 G[4][4], const M2& R) {
#pragma unroll
    for (int c = 0; c < 4; ++c) {
        float2 t2 = G[2][c], t3 = G[3][c];
        G[2][c] = cadd2(cmul2(R.m[0][0], t2), cmul2(R.m[0][1], t3));
        G[3][c] = cadd2(cmul2(R.m[1][0], t2), cmul2(R.m[1][1], t3));
    }
}
__device__ __forceinline__ void tgtH_mul(float2 G[4][4], const M2& R) {
#pragma unroll
    for (int c = 0; c < 4; ++c) {
#pragma unroll
        for (int aL = 0; aL < 2; ++aL) {
            float2 t0 = G[aL][c], t1 = G[2 + aL][c];
            G[aL][c]     = cadd2(cmul2(R.m[0][0], t0), cmul2(R.m[0][1], t1));
            G[2 + aL][c] = cadd2(cmul2(R.m[1][0], t0), cmul2(R.m[1][1], t1));
        }
    }
}
__device__ __forceinline__ void extractA(const float2 G[4][4], int bL, float* A, float* B) {
    float2 a0 = bL ? G[1][1] : G[0][0], a1 = bL ? G[1][0] : G[0][1];
    float2 a2 = bL ? G[1][3] : G[0][2], a3 = bL ? G[1][2] : G[0][3];
    A[0]=a0.x; A[1]=a0.y; A[2]=a1.x; A[3]=a1.y; A[4]=a2.x; A[5]=a2.y; A[6]=a3.x; A[7]=a3.y;
    float2 b0 = bL ? G[3][1] : G[2][0], b1 = bL ? G[3][0] : G[2][1];
    float2 b2 = bL ? G[3][3] : G[2][2], b3 = bL ? G[3][2] : G[2][3];
    B[0]=b0.x; B[1]=b0.y; B[2]=b1.x; B[3]=b1.y; B[4]=b2.x; B[5]=b2.y; B[6]=b3.x; B[7]=b3.y;
}
__device__ __forceinline__ void extractP(const float2 G[4][4], int bH, int bL, float* C) {
    int d = 2*bH + bL;
#pragma unroll
    for (int j = 0; j < 4; ++j) {
        float2 c = (d == 0) ? G[0][j] : (d == 1) ? G[1][1^j] : (d == 2) ? G[2][2^j] : G[3][3^j];
        C[2*j] = c.x; C[2*j + 1] = c.y;
    }
}

// ---------------- runtime gate primitives ----------------
__device__ __forceinline__ void applyA(float& r0, float& i0, float& r1, float& i1,
                                       int mL, const float* A, const float* B) {
    float p0 = SH(r0, mL), q0 = SH(i0, mL), p1 = SH(r1, mL), q1 = SH(i1, mL);
    float nr0 = A[0]*r0 - A[1]*i0 + A[2]*p0 - A[3]*q0 + A[4]*r1 - A[5]*i1 + A[6]*p1 - A[7]*q1;
    float ni0 = A[0]*i0 + A[1]*r0 + A[2]*q0 + A[3]*p0 + A[4]*i1 + A[5]*r1 + A[6]*q1 + A[7]*p1;
    float nr1 = B[0]*r0 - B[1]*i0 + B[2]*p0 - B[3]*q0 + B[4]*r1 - B[5]*i1 + B[6]*p1 - B[7]*q1;
    float ni1 = B[0]*i0 + B[1]*r0 + B[2]*q0 + B[3]*p0 + B[4]*i1 + B[5]*r1 + B[6]*q1 + B[7]*p1;
    r0 = nr0; i0 = ni0; r1 = nr1; i1 = ni1;
}
__device__ __forceinline__ void applyP(float& r0, float& i0, float& r1, float& i1,
                                       int mH, int mL, const float* C) {
    const int mHL = mH | mL;
    float Ar0 = SH(r0, mL),  Ai0 = SH(i0, mL),  Ar1 = SH(r1, mL),  Ai1 = SH(i1, mL);
    float Br0 = SH(r0, mH),  Bi0 = SH(i0, mH),  Br1 = SH(r1, mH),  Bi1 = SH(i1, mH);
    float Cr0 = SH(r0, mHL), Ci0 = SH(i0, mHL), Cr1 = SH(r1, mHL), Ci1 = SH(i1, mHL);
    float nr0 = C[0]*r0 - C[1]*i0 + C[2]*Ar0 - C[3]*Ai0 + C[4]*Br0 - C[5]*Bi0 + C[6]*Cr0 - C[7]*Ci0;
    float ni0 = C[0]*i0 + C[1]*r0 + C[2]*Ai0 + C[3]*Ar0 + C[4]*Bi0 + C[5]*Br0 + C[6]*Ci0 + C[7]*Cr0;
    float nr1 = C[0]*r1 - C[1]*i1 + C[2]*Ar1 - C[3]*Ai1 + C[4]*Br1 - C[5]*Bi1 + C[6]*Cr1 - C[7]*Ci1;
    float ni1 = C[0]*i1 + C[1]*r1 + C[2]*Ai1 + C[3]*Ar1 + C[4]*Bi1 + C[5]*Br1 + C[6]*Ci1 + C[7]*Cr1;
    r0 = nr0; i0 = ni0; r1 = nr1; i1 = ni1;
}
__device__ __forceinline__ void crx_gen(float& r0, float& i0, float& r1, float& i1,
                                        int m, float cE, float sE) {
    float pr0 = SH(r0, m), pi0 = SH(i0, m), pr1 = SH(r1, m), pi1 = SH(i1, m);
    float nr0 = cE*r0 + sE*pi0, ni0 = cE*i0 - sE*pr0;
    float nr1 = cE*r1 + sE*pi1, ni1 = cE*i1 - sE*pr1;
    r0 = nr0; i0 = ni0; r1 = nr1; i1 = ni1;
}
__device__ __forceinline__ void crx_treg(float& r0, float& i0, float& r1, float& i1,
                                         float cE, float sE) {
    float nr0 = cE*r0 + sE*i1, ni0 = cE*i0 - sE*r1;
    float nr1 = cE*r1 + sE*i0, ni1 = cE*i1 - sE*r0;
    r0 = nr0; i0 = ni0; r1 = nr1; i1 = ni1;
}
__device__ __forceinline__ void crx_cb5(float& r1, float& i1, int m, float c, float s) {
    float p = SH(r1, m), q = SH(i1, m);
    float nr1 = fmaf(s, q, c * r1);
    float ni1 = fmaf(-s, p, c * i1);
    r1 = nr1; i1 = ni1;
}

// ---------------- main sim: one warp per chain ----------------
__global__ void __launch_bounds__(32, 1)
sim_kernel(const float* __restrict__ angles,
           const float* __restrict__ Dv_in,
           float* __restrict__ out) {
    const int b    = blockIdx.x;
    const int lane = threadIdx.x;

    // ---- composed QSVT: sigma^4 source indices + per-amp phase coefficients B ----
    int fwd[64];
    for (int s = 0; s < 64; ++s) {
        int q[6];
#pragma unroll
        for (int i = 0; i < 6; ++i) q[i] = (s >> (5 - i)) & 1;
        q[1]^=q[0]; q[2]^=q[1]; q[3]^=q[2]; q[4]^=q[3]; q[5]^=q[4];
        q[0]^=q[5]; q[4]^=q[5]; q[3]^=q[4]; q[2]^=q[3]; q[1]^=q[2]; q[0]^=q[1];
        int tt = 0;
#pragma unroll
        for (int i = 0; i < 6; ++i) tt |= q[i] << (5 - i);
        fwd[s] = tt;
    }
    int inv[64];
    for (int s = 0; s < 64; ++s) inv[fwd[s]] = s;

    float B0[6] = {0,0,0,0,0,0}, B1[6] = {0,0,0,0,0,0};
    int u0 = lane, u1 = lane + 32;
    for (int k = 1; k <= 4; ++k) {
        u0 = inv[u0]; u1 = inv[u1];
        int d = 4 - k;
#pragma unroll
        for (int i = 0; i < 6; ++i) {
            float c = 0.5f * g_tf[d * 6 + i];
            B0[i] += ((u0 >> (5 - i)) & 1) ? c : -c;
            B1[i] += ((u1 >> (5 - i)) & 1) ? c : -c;
        }
    }
    const int s40 = u0, s41 = u1;

    int lbit[5];
#pragma unroll
    for (int bp = 0; bp < 5; ++bp) lbit[bp] = (lane >> bp) & 1;
    // qubit bits: q1=lbit[4], q2=lbit[3], q3=lbit[2], q4=lbit[1], q5=lbit[0]

    // ---- build per-lane block-gate coefficients (one-time) ----
    float Aa[2][8], Ab[2][8], Bc[2][8], Cc[2][8];
    float f0c[2], f0s[2], C5c[2], C5s[2];
    float dgc[8], dgs[8];
#pragma unroll
    for (int L = 0; L < 2; ++L) {
        M2 T0 = mkT(g_fa[L*6+0], g_fb[L*6+0]);
        M2 T1 = mkT(g_fa[L*6+1], g_fb[L*6+1]);
        M2 T2 = mkT(g_fa[L*6+2], g_fb[L*6+2]);
        M2 T3 = mkT(g_fa[L*6+3], g_fb[L*6+3]);
        M2 T4 = mkT(g_fa[L*6+4], g_fb[L*6+4]);
        M2 T5 = mkT(g_fa[L*6+5], g_fb[L*6+5]);
        float2 cs;
        cs = g_crx[L*12+0];  M2 R01 = mkRX(cs.x, cs.y);
        cs = g_crx[L*12+1];  M2 R12c = mkRX(lbit[4] ? cs.x : 1.f, lbit[4] ? cs.y : 0.f);
        cs = g_crx[L*12+2];  M2 R23 = mkRX(cs.x, cs.y);
        cs = g_crx[L*12+3];  M2 R34c = mkRX(lbit[2] ? cs.x : 1.f, lbit[2] ? cs.y : 0.f);
        cs = g_crx[L*12+4];  M2 R45 = mkRX(cs.x, cs.y);
        // fused CRX(5,0)*CRX(1,0): both RX on reg qubit, per-lane angles add
        float uc, us, dc, ds;
        cs = g_crx[L*12+5];  uc = lbit[0] ? cs.x : 1.f;  us = lbit[0] ? cs.y : 0.f;
        cs = g_crx[L*12+10]; dc = lbit[4] ? cs.x : 1.f;  ds = lbit[4] ? cs.y : 0.f;
        f0c[L] = uc * dc - us * ds;
        f0s[L] = us * dc + uc * ds;
#pragma unroll
        for (int j = 0; j < 4; ++j) {   // down-ring generals: ctrl bp j, tgt mask 2<<j
            float2 c2 = g_crx[L*12 + 6 + j]; int p = lbit[j];
            dgc[L*4 + j] = p ? c2.x : 1.f;  dgs[L*4 + j] = p ? c2.y : 0.f;
        }
        cs = g_crx[L*12+11]; C5c[L] = cs.x; C5s[L] = cs.y;

        float2 G[4][4];
        kron4(G, T0, T1); ctrlH_mul(G, R01);
        extractA(G, lbit[4], Aa[L], Ab[L]);
        kron4(G, T2, T3); tgtH_mul(G, R12c); ctrlH_mul(G, R23);
        extractP(G, lbit[3], lbit[2], Bc[L]);
        kron4(G, T4, T5); tgtH_mul(G, R34c); ctrlH_mul(G, R45);
        extractP(G, lbit[1], lbit[0], Cc[L]);
    }

    // gather source lanes + per-lane signs
    int srcZi = 26;
    if (lane == 7)  srcZi = 16;
    if (lane == 8)  srcZi = 24;
    if (lane == 9)  srcZi = 20;
    if (lane == 10) srcZi = 28;
    if (lane == 11) srcZi = 18;
    const int qsel = lane % 6;
    const int srcZr = (qsel==0)?10:(qsel==1)?0:(qsel==2)?8:(qsel==3)?4:(qsel==4)?12:2;
    const int srcF  = (qsel==0)?0:(32 >> qsel);
    float sgm[5];
#pragma unroll
    for (int i = 1; i <= 5; ++i)
        sgm[i-1] = ((lane >> (5 - i)) & 1) ? -1.f : 1.f;

    const float*  angB = angles + (size_t)b * SEQ * 6;
    const float4* pkB  = g_pk   + (size_t)b * SEQ * 2;
    const float2* csB  = g_cs2  + (size_t)b * SEQ * 6;
    const float*  cwB  = g_cw   + (size_t)b * SEQ * 18;
    float*        outB = out    + (size_t)b * SEQ * 18;
    const float   Dme  = (lane < 18) ? Dv_in[lane] : 0.f;

    // preload t=0 inputs
    float4 f0 = __ldg(pkB + 0), f1 = __ldg(pkB + 1);
    float2 ecs = __ldg(csB + qsel);
    float cwv = (lane < 18) ? __ldg(cwB + lane) : 0.f;
    float xme = (lane < 18) ? __ldg(angB + qsel) : 0.f;

    // h-state carried as broadcast sincos (h=0 at t=0)
    float hcv[6] = {1.f,1.f,1.f,1.f,1.f,1.f};
    float hsv[6] = {0.f,0.f,0.f,0.f,0.f,0.f};

#pragma unroll 1
    for (int t = 0; t < SEQ; ++t) {
        // ---- prefetch next step's inputs ----
        const int tn = (t + 1 < SEQ) ? t + 1 : t;
        float4 f0n = __ldg(pkB + tn*2 + 0), f1n = __ldg(pkB + tn*2 + 1);
        float2 ecsn = __ldg(csB + tn*6 + qsel);
        float cwn = (lane < 18) ? __ldg(cwB + tn*18 + lane) : 0.f;
        float xmn = (lane < 18) ? __ldg(angB + tn*6 + qsel) : 0.f;

        float dta[6] = {f0.x, f0.y, f0.z, f0.w, f1.x, f1.y};

        // ---- QSVT phase ----
        float acc0 = B0[0] * dta[0], acc1 = B1[0] * dta[0];
#pragma unroll
        for (int i = 1; i < 6; ++i) {
            acc0 = fmaf(B0[i], dta[i], acc0);
            acc1 = fmaf(B1[i], dta[i], acc1);
        }
        float c0, s0, c1, s1;
        __sincosf(acc0, &s0, &c0);
        __sincosf(acc1, &s1, &c1);

        // ---- initial RY(h) product state at sigma^{-4} indices, times QSVT phase ----
        float pr0 = 1.f, pr1 = 1.f;
#pragma unroll
        for (int i = 0; i < 6; ++i) {
            pr0 *= ((s40 >> (5 - i)) & 1) ? hsv[i] : hcv[i];
            pr1 *= ((s41 >> (5 - i)) & 1) ? hsv[i] : hcv[i];
        }
        float r0 = pr0 * c0, i0 = pr0 * s0;
        float r1 = pr1 * c1, i1 = pr1 * s1;

        // ---- ansatz: 2 layers ----
#pragma unroll
        for (int L = 0; L < 2; ++L) {
            applyA(r0, i0, r1, i1, 16, Aa[L], Ab[L]);      // CRX01 * T0xT1
            applyP(r0, i0, r1, i1, 8, 4, Bc[L]);           // CRX23*CRX12*T2xT3
            applyP(r0, i0, r1, i1, 2, 1, Cc[L]);           // CRX45*CRX34*T4xT5
            crx_gen(r0, i0, r1, i1, 2,  dgc[L*4+0], dgs[L*4+0]);  // CRX(5,4)
            crx_gen(r0, i0, r1, i1, 4,  dgc[L*4+1], dgs[L*4+1]);  // CRX(4,3)
            crx_gen(r0, i0, r1, i1, 8,  dgc[L*4+2], dgs[L*4+2]);  // CRX(3,2)
            crx_gen(r0, i0, r1, i1, 16, dgc[L*4+3], dgs[L*4+3]);  // CRX(2,1)
            crx_treg(r0, i0, r1, i1, f0c[L], f0s[L]);      // CRX(5,0)*CRX(1,0) fused
            crx_cb5(r1, i1, 1, C5c[L], C5s[L]);            // CRX(0,5)
        }

        // ---- measurements ----
        float w0 = r0*r0 + i0*i0;
        float w1 = r1*r1 + i1*i1;
        float ws = w0 + w1, wd = w0 - w1;
        float f = ws;
#pragma unroll
        for (int st = 0; st < 5; ++st) {
            int m = 16 >> st;
            float p = SH(f, m);
            f = (lane & m) ? (p - f) : (f + p);
        }

        // pair products: vr = symmetric (sums to 2x), vi = signed antisym (sums to 2x)
        float vr[5], vi[5];
#pragma unroll
        for (int i = 1; i <= 5; ++i) {
            int m = 1 << (5 - i);
            float pr0s = SH(r0, m), pi0s = SH(i0, m), pr1s = SH(r1, m), pi1s = SH(i1, m);
            float u = r0*pr0s + i0*pi0s + r1*pr1s + i1*pi1s;
            float v = r0*pi0s - i0*pr0s + r1*pi1s - i1*pr1s;
            vr[i-1] = u;
            vi[i-1] = sgm[i-1] * v;
        }
        float zr0 = r0*r1 + i0*i1;  zr0 += zr0;   // 2x to match
        float zi0 = r0*i1 - i0*r1;  zi0 += zi0;

        // packed reduction tree (all sums are 2x targets except wd/f which are 1x)
        float P1, P2, P3, P4, P5, P6, P7;
        { float a = vr[0] + SH(vr[0],16), bb = vi[0] + SH(vi[0],16); P1 = (lane&16) ? bb : a; }
        { float a = vr[1] + SH(vr[1],16), bb = vi[1] + SH(vi[1],16); P2 = (lane&16) ? bb : a; }
        { float a = vr[2] + SH(vr[2],16), bb = vi[2] + SH(vi[2],16); P3 = (lane&16) ? bb : a; }
        { float a = vr[3] + SH(vr[3],16), bb = vi[3] + SH(vi[3],16); P4 = (lane&16) ? bb : a; }
        { float a = vr[4] + SH(vr[4],16), bb = vi[4] + SH(vi[4],16); P5 = (lane&16) ? bb : a; }
        { float a = zr0   + SH(zr0,  16), bb = zi0   + SH(zi0,  16); P6 = (lane&16) ? bb : a; }
        P7 = wd + SH(wd, 16);
        float Q1, Q2, Q3, Q4;
        { float a = P1 + SH(P1,8), bb = P2 + SH(P2,8); Q1 = (lane&8) ? bb : a; }
        { float a = P3 + SH(P3,8), bb = P4 + SH(P4,8); Q2 = (lane&8) ? bb : a; }
        { float a = P5 + SH(P5,8), bb = P6 + SH(P6,8); Q3 = (lane&8) ? bb : a; }
        Q4 = P7 + SH(P7, 8);
        float R1, R2;
        { float a = Q1 + SH(Q1,4), bb = Q2 + SH(Q2,4); R1 = (lane&4) ? bb : a; }
        { float a = Q3 + SH(Q3,4), bb = Q4 + SH(Q4,4); R2 = (lane&4) ? bb : a; }
        float Sv;
        { float a = R1 + SH(R1,2), bb = R2 + SH(R2,2); Sv = (lane&2) ? bb : a; }
        Sv += SH(Sv, 1);
        // Sv lane map: zr2x:{q0:10,q1:0,q2:8,q3:4,q4:12,q5:2}, zi2x=+16, wd@6

        // per-lane gathers only
        float tF  = __shfl_sync(FULLM, f,  srcF);
        float tW  = __shfl_sync(FULLM, Sv, 6);
        float ztsel = qsel ? tF : tW;
        float zrsel = __shfl_sync(FULLM, Sv, srcZr);   // = 2*zr[qsel]
        float giZ   = __shfl_sync(FULLM, Sv, srcZi);   // = 2*zi
        float csel = ecs.x, ssel = ecs.y;

        float hq   = csel * ztsel - ssel * zrsel;      // h[qsel]
        float mval = (lane < 6)  ? fmaf(csel, zrsel, ssel * ztsel)
                   : (lane < 12) ? giZ
                                 : hq;
        if (lane < 18)
            outB[t * 18 + lane] = cwv * mval + Dme * xme;

        // next-state: sincos of h[qsel], broadcast qubits 0..5
        float hs_, hc_;
        __sincosf(0.5f * hq, &hs_, &hc_);
#pragma unroll
        for (int i = 0; i < 6; ++i) {
            hcv[i] = __shfl_sync(FULLM, hc_, i);
            hsv[i] = __shfl_sync(FULLM, hs_, i);
        }

        // rotate prefetched inputs in
        f0 = f0n; f1 = f1n; ecs = ecsn; cwv = cwn; xme = xmn;
    }
}

// ---------------- launch ----------------
extern "C" void kernel_launch(void* const* d_in, const int* in_sizes, int n_in,
                              void* d_out, int out_size) {
    const float* angles = (const float*)d_in[0];
    const float* Wx     = (const float*)d_in[1];
    const float* Wdt    = (const float*)d_in[2];
    const float* bdt    = (const float*)d_in[3];
    const float* pc     = (const float*)d_in[4];
    const float* qp     = (const float*)d_in[5];
    const float* cp     = (const float*)d_in[6];
    const float* D      = (const float*)d_in[7];
    const float* Wc     = (const float*)d_in[8];

    prep_kernel <<<(BATCH * SEQ + 255) / 256, 256>>>(angles, Wx, Wdt, bdt, Wc);
    prep2_kernel<<<1, 64>>>(pc, qp, cp);
    sim_kernel  <<<BATCH, 32>>>(angles, D, (float*)d_out);
}

// round 16
// speedup vs baseline: 1.2692x; 1.0142x over previous
#include <cuda_runtime.h>
#include <cstdint>

#define NQ     6
#define BATCH  256
#define SEQ    512
#define FULLM  0xffffffffu
#define PI_F   3.14159265358979323846f
#define SH(v,m) __shfl_xor_sync(FULLM, (v), (m))
typedef unsigned long long ull;

// ---------------- scratch ----------------
__device__ float4 g_pk [BATCH * SEQ * 2];
__device__ float2 g_cs2[BATCH * SEQ * 6];
__device__ float  g_cw [BATCH * SEQ * 18];
__device__ float  g_tf [24];
__device__ float2 g_fa [12];
__device__ float2 g_fb [12];
__device__ float2 g_crx[24];

// ---------------- prep 1 ----------------
__global__ void prep_kernel(const float* __restrict__ angles,
                            const float* __restrict__ Wx,
                            const float* __restrict__ Wdt,
                            const float* __restrict__ bdt,
                            const float* __restrict__ Wc) {
    int idx = blockIdx.x * blockDim.x + threadIdx.x;
    if (idx >= BATCH * SEQ) return;
    float a[6];
#pragma unroll
    for (int k = 0; k < 6; ++k) a[k] = angles[idx * 6 + k];
    float dtr[3];
#pragma unroll
    for (int r = 0; r < 3; ++r) {
        float s = 0.f;
#pragma unroll
        for (int k = 0; k < 6; ++k) s += a[k] * Wx[r * 6 + k];
        dtr[r] = s;
    }
    float C[6];
#pragma unroll
    for (int j = 0; j < 6; ++j) {
        float s = 0.f;
#pragma unroll
        for (int k = 0; k < 6; ++k) s += a[k] * Wx[(9 + j) * 6 + k];
        C[j] = s;
    }
    float dta[6];
#pragma unroll
    for (int i = 0; i < 6; ++i) {
        float v = bdt[i];
#pragma unroll
        for (int r = 0; r < 3; ++r) v += dtr[r] * Wdt[i * 3 + r];
        float sp = (v > 20.f) ? v : log1pf(expf(v));
        dta[i] = tanhf(sp) * PI_F;
    }
    g_pk[idx * 2 + 0] = make_float4(dta[0], dta[1], dta[2], dta[3]);
    g_pk[idx * 2 + 1] = make_float4(dta[4], dta[5], 0.f, 0.f);
#pragma unroll
    for (int i = 0; i < 6; ++i) {
        float cv, sv;
        __sincosf(a[i] * dta[i], &sv, &cv);
        g_cs2[idx * 6 + i] = make_float2(cv, sv);
    }
#pragma unroll
    for (int j = 0; j < 18; ++j) {
        float s = 0.f;
#pragma unroll
        for (int k = 0; k < 6; ++k) s += C[k] * Wc[j * 6 + k];
        g_cw[idx * 18 + j] = s;
    }
}

// ---------------- prep 2 ----------------
__global__ void prep2_kernel(const float* __restrict__ pc,
                             const float* __restrict__ qp,
                             const float* __restrict__ cp) {
    int t = threadIdx.x;
    if (t < 24) {
        int d = t / 6, i = t % 6;
        g_tf[t] = pc[d] * PI_F * ((d < 3) ? qp[d * 6 + i] : 1.0f);
    }
    if (t < 24) {
        int L = t / 12, k = t % 12;
        float ang = (k < 6) ? cp[L * 30 + 18 + k] : cp[L * 30 + 24 + (k - 6)];
        float th = 0.5f * ang;
        g_crx[t] = make_float2(cosf(th), sinf(th));
    }
    if (t < 12) {
        int L = t / 6, i = t % 6, base = L * 30 + i * 3;
        float cx = cosf(0.5f * cp[base]),     sx = sinf(0.5f * cp[base]);
        float cy = cosf(0.5f * cp[base + 1]), sy = sinf(0.5f * cp[base + 1]);
        float cz = cosf(0.5f * cp[base + 2]), sz = sinf(0.5f * cp[base + 2]);
        float M00r = cy * cx, M00i = sy * sx;
        float M10r = sy * cx, M10i = -cy * sx;
        g_fa[t] = make_float2(cz * M00r + sz * M00i, cz * M00i - sz * M00r);
        g_fb[t] = make_float2(cz * M10r - sz * M10i, cz * M10i + sz * M10r);
    }
}

// ---------------- f32x2 helpers ----------------
__device__ __forceinline__ ull packf(float lo, float hi) {
    ull u; asm("mov.b64 %0, {%1, %2};" : "=l"(u) : "f"(lo), "f"(hi)); return u;
}
__device__ __forceinline__ void unpackf(ull v, float& lo, float& hi) {
    asm("mov.b64 {%0, %1}, %2;" : "=f"(lo), "=f"(hi) : "l"(v));
}
__device__ __forceinline__ ull swap64(ull v) {
    ull o;
    asm("{\n\t.reg .b32 sl, sh;\n\tmov.b64 {sl, sh}, %1;\n\tmov.b64 %0, {sh, sl};\n\t}"
        : "=l"(o) : "l"(v));
    return o;
}
#define FMA2(d,a,b,c) asm("fma.rn.f32x2 %0, %1, %2, %3;" : "=l"(d) : "l"(a), "l"(b), "l"(c))
#define MUL2(d,a,b)   asm("mul.rn.f32x2 %0, %1, %2;"     : "=l"(d) : "l"(a), "l"(b))
#define SUB2(d,a,b)   asm("sub.rn.f32x2 %0, %1, %2;"     : "=l"(d) : "l"(a), "l"(b))

// ---------------- complex / matrix helpers (prologue only) ----------------
__device__ __forceinline__ float2 cmul2(float2 a, float2 b) {
    return make_float2(a.x*b.x - a.y*b.y, a.x*b.y + a.y*b.x);
}
__device__ __forceinline__ float2 cadd2(float2 a, float2 b) {
    return make_float2(a.x + b.x, a.y + b.y);
}
struct M2 { float2 m[2][2]; };
__device__ __forceinline__ M2 mkT(float2 al, float2 be) {
    M2 t;
    t.m[0][0] = al; t.m[0][1] = make_float2(-be.x, be.y);
    t.m[1][0] = be; t.m[1][1] = make_float2(al.x, -al.y);
    return t;
}
__device__ __forceinline__ M2 mkRX(float c, float s) {
    M2 t;
    t.m[0][0] = make_float2(c, 0.f); t.m[0][1] = make_float2(0.f, -s);
    t.m[1][0] = make_float2(0.f, -s); t.m[1][1] = make_float2(c, 0.f);
    return t;
}
__device__ __forceinline__ void kron4(float2 G[4][4], const M2& A, const M2& B) {
#pragma unroll
    for (int i = 0; i < 2; ++i)
#pragma unroll
    for (int j = 0; j < 2; ++j)
#pragma unroll
    for (int k = 0; k < 2; ++k)
#pragma unroll
    for (int l = 0; l < 2; ++l)
        G[2*i + k][2*j + l] = cmul2(A.m[i][j], B.m[k][l]);
}
__device__ __forceinline__ void ctrlH_mul(float2 G[4][4], const M2& R) {
#pragma unroll
    for (int c = 0; c < 4; ++c) {
        float2 t2 = G[2][c], t3 = G[3][c];
        G[2][c] = cadd2(cmul2(R.m[0][0], t2), cmul2(R.m[0][1], t3));
        G[3][c] = cadd2(cmul2(R.m[1][0], t2), cmul2(R.m[1][1], t3));
    }
}
__device__ __forceinline__ void tgtH_mul(float2 G[4][4], const M2& R) {
#pragma unroll
    for (int c = 0; c < 4; ++c) {
#pragma unroll
        for (int aL = 0; aL < 2; ++aL) {
            float2 t0 = G[aL][c], t1 = G[2 + aL][c];
            G[aL][c]     = cadd2(cmul2(R.m[0][0], t0), cmul2(R.m[0][1], t1));
            G[2 + aL][c] = cadd2(cmul2(R.m[1][0], t0), cmul2(R.m[1][1], t1));
        }
    }
}
__device__ __forceinline__ void extractA(const float2 G[4][4], int bL, float* A, float* B) {
    float2 a0 = bL ? G[1][1] : G[0][0], a1 = bL ? G[1][0] : G[0][1];
    float2 a2 = bL ? G[1][3] : G[0][2], a3 = bL ? G[1][2] : G[0][3];
    A[0]=a0.x; A[1]=a0.y; A[2]=a1.x; A[3]=a1.y; A[4]=a2.x; A[5]=a2.y; A[6]=a3.x; A[7]=a3.y;
    float2 b0 = bL ? G[3][1] : G[2][0], b1 = bL ? G[3][0] : G[2][1];
    float2 b2 = bL ? G[3][3] : G[2][2], b3 = bL ? G[3][2] : G[2][3];
    B[0]=b0.x; B[1]=b0.y; B[2]=b1.x; B[3]=b1.y; B[4]=b2.x; B[5]=b2.y; B[6]=b3.x; B[7]=b3.y;
}
__device__ __forceinline__ void extractP(const float2 G[4][4], int bH, int bL, float* C) {
    int d = 2*bH + bL;
#pragma unroll
    for (int j = 0; j < 4; ++j) {
        float2 c = (d == 0) ? G[0][j] : (d == 1) ? G[1][1^j] : (d == 2) ? G[2][2^j] : G[3][3^j];
        C[2*j] = c.x; C[2*j + 1] = c.y;
    }
}

// ---------------- runtime gate primitives ----------------
__device__ __forceinline__ void applyA(float& r0, float& i0, float& r1, float& i1,
                                       int mL, const float* A, const float* B) {
    float p0 = SH(r0, mL), q0 = SH(i0, mL), p1 = SH(r1, mL), q1 = SH(i1, mL);
    float nr0 = A[0]*r0 - A[1]*i0 + A[2]*p0 - A[3]*q0 + A[4]*r1 - A[5]*i1 + A[6]*p1 - A[7]*q1;
    float ni0 = A[0]*i0 + A[1]*r0 + A[2]*q0 + A[3]*p0 + A[4]*i1 + A[5]*r1 + A[6]*q1 + A[7]*p1;
    float nr1 = B[0]*r0 - B[1]*i0 + B[2]*p0 - B[3]*q0 + B[4]*r1 - B[5]*i1 + B[6]*p1 - B[7]*q1;
    float ni1 = B[0]*i0 + B[1]*r0 + B[2]*q0 + B[3]*p0 + B[4]*i1 + B[5]*r1 + B[6]*q1 + B[7]*p1;
    r0 = nr0; i0 = ni0; r1 = nr1; i1 = ni1;
}
// packed pair gate: P=(r0,r1), Q=(i0,i1); CR[j]=(cr,cr), CIN[j]=(-ci,-ci)
__device__ __forceinline__ void applyP2(ull& P, ull& Q, int mH, int mL,
                                        const ull* CR, const ull* CIN) {
    const int mHL = mH | mL;
    ull AP = SH(P, mL),  AQ = SH(Q, mL);
    ull BP = SH(P, mH),  BQ = SH(Q, mH);
    ull CP_ = SH(P, mHL), CQ_ = SH(Q, mHL);
    ull nP;
    MUL2(nP, CR[0], P);       FMA2(nP, CIN[0], Q,  nP);
    FMA2(nP, CR[1], AP, nP);  FMA2(nP, CIN[1], AQ, nP);
    FMA2(nP, CR[2], BP, nP);  FMA2(nP, CIN[2], BQ, nP);
    FMA2(nP, CR[3], CP_, nP); FMA2(nP, CIN[3], CQ_, nP);
    ull u, v, nQ;
    MUL2(u, CR[0], Q);   FMA2(u, CR[1], AQ, u);  FMA2(u, CR[2], BQ, u);  FMA2(u, CR[3], CQ_, u);
    MUL2(v, CIN[0], P);  FMA2(v, CIN[1], AP, v); FMA2(v, CIN[2], BP, v); FMA2(v, CIN[3], CP_, v);
    SUB2(nQ, u, v);
    P = nP; Q = nQ;
}
// packed single-mask CRX: CP=(c,c), SP=(s,s)
__device__ __forceinline__ void crx_gen2(ull& P, ull& Q, int m, ull CP, ull SP) {
    ull shP = SH(P, m), shQ = SH(Q, m);
    ull t, u, v, nP, nQ;
    MUL2(t, CP, P);  FMA2(nP, SP, shQ, t);
    MUL2(u, CP, Q);  MUL2(v, SP, shP);  SUB2(nQ, u, v);
    P = nP; Q = nQ;
}
// packed reg-target CRX: swap across the pair
__device__ __forceinline__ void crx_treg2(ull& P, ull& Q, ull CP, ull SP) {
    ull swP = swap64(P), swQ = swap64(Q);
    ull t, u, v, nP, nQ;
    MUL2(t, CP, P);  FMA2(nP, SP, swQ, t);
    MUL2(u, CP, Q);  MUL2(v, SP, swP);  SUB2(nQ, u, v);
    P = nP; Q = nQ;
}
__device__ __forceinline__ void crx_cb5(float& r1, float& i1, int m, float c, float s) {
    float p = SH(r1, m), q = SH(i1, m);
    float nr1 = fmaf(s, q, c * r1);
    float ni1 = fmaf(-s, p, c * i1);
    r1 = nr1; i1 = ni1;
}

// ---------------- main sim: one warp per chain ----------------
__global__ void __launch_bounds__(32, 1)
sim_kernel(const float* __restrict__ angles,
           const float* __restrict__ Dv_in,
           float* __restrict__ out) {
    const int b    = blockIdx.x;
    const int lane = threadIdx.x;

    // ---- composed QSVT permutation + phase coefficients ----
    int fwd[64];
    for (int s = 0; s < 64; ++s) {
        int q[6];
#pragma unroll
        for (int i = 0; i < 6; ++i) q[i] = (s >> (5 - i)) & 1;
        q[1]^=q[0]; q[2]^=q[1]; q[3]^=q[2]; q[4]^=q[3]; q[5]^=q[4];
        q[0]^=q[5]; q[4]^=q[5]; q[3]^=q[4]; q[2]^=q[3]; q[1]^=q[2]; q[0]^=q[1];
        int tt = 0;
#pragma unroll
        for (int i = 0; i < 6; ++i) tt |= q[i] << (5 - i);
        fwd[s] = tt;
    }
    int inv[64];
    for (int s = 0; s < 64; ++s) inv[fwd[s]] = s;

    float B0[6] = {0,0,0,0,0,0}, B1[6] = {0,0,0,0,0,0};
    int u0 = lane, u1 = lane + 32;
    for (int k = 1; k <= 4; ++k) {
        u0 = inv[u0]; u1 = inv[u1];
        int d = 4 - k;
#pragma unroll
        for (int i = 0; i < 6; ++i) {
            float c = 0.5f * g_tf[d * 6 + i];
            B0[i] += ((u0 >> (5 - i)) & 1) ? c : -c;
            B1[i] += ((u1 >> (5 - i)) & 1) ? c : -c;
        }
    }
    const int s40 = u0, s41 = u1;

    int lbit[5];
#pragma unroll
    for (int bp = 0; bp < 5; ++bp) lbit[bp] = (lane >> bp) & 1;

    // ---- per-lane gate coefficients ----
    float Aa[2][8], Ab[2][8];
    ull  BcR[2][4], BcI[2][4], CcR[2][4], CcI[2][4];
    ull  gCP[8], gSP[8], tCP[2], tSP[2];
    float C5c[2], C5s[2];
#pragma unroll
    for (int L = 0; L < 2; ++L) {
        M2 T0 = mkT(g_fa[L*6+0], g_fb[L*6+0]);
        M2 T1 = mkT(g_fa[L*6+1], g_fb[L*6+1]);
        M2 T2 = mkT(g_fa[L*6+2], g_fb[L*6+2]);
        M2 T3 = mkT(g_fa[L*6+3], g_fb[L*6+3]);
        M2 T4 = mkT(g_fa[L*6+4], g_fb[L*6+4]);
        M2 T5 = mkT(g_fa[L*6+5], g_fb[L*6+5]);
        float2 cs;
        cs = g_crx[L*12+0];  M2 R01 = mkRX(cs.x, cs.y);
        cs = g_crx[L*12+1];  M2 R12c = mkRX(lbit[4] ? cs.x : 1.f, lbit[4] ? cs.y : 0.f);
        cs = g_crx[L*12+2];  M2 R23 = mkRX(cs.x, cs.y);
        cs = g_crx[L*12+3];  M2 R34c = mkRX(lbit[2] ? cs.x : 1.f, lbit[2] ? cs.y : 0.f);
        cs = g_crx[L*12+4];  M2 R45 = mkRX(cs.x, cs.y);
        // fused CRX(5,0)*CRX(1,0): per-lane angle add, packed
        float uc, us, dc, ds;
        cs = g_crx[L*12+5];  uc = lbit[0] ? cs.x : 1.f;  us = lbit[0] ? cs.y : 0.f;
        cs = g_crx[L*12+10]; dc = lbit[4] ? cs.x : 1.f;  ds = lbit[4] ? cs.y : 0.f;
        float fc = uc * dc - us * ds, fs = us * dc + uc * ds;
        tCP[L] = packf(fc, fc);  tSP[L] = packf(fs, fs);
#pragma unroll
        for (int j = 0; j < 4; ++j) {
            float2 c2 = g_crx[L*12 + 6 + j]; int p = lbit[j];
            float cc = p ? c2.x : 1.f, ss = p ? c2.y : 0.f;
            gCP[L*4 + j] = packf(cc, cc);  gSP[L*4 + j] = packf(ss, ss);
        }
        cs = g_crx[L*12+11]; C5c[L] = cs.x; C5s[L] = cs.y;

        float2 G[4][4];
        kron4(G, T0, T1); ctrlH_mul(G, R01);
        extractA(G, lbit[4], Aa[L], Ab[L]);
        float Cs[8];
        kron4(G, T2, T3); tgtH_mul(G, R12c); ctrlH_mul(G, R23);
        extractP(G, lbit[3], lbit[2], Cs);
#pragma unroll
        for (int j = 0; j < 4; ++j) {
            BcR[L][j] = packf(Cs[2*j], Cs[2*j]);
            BcI[L][j] = packf(-Cs[2*j+1], -Cs[2*j+1]);
        }
        kron4(G, T4, T5); tgtH_mul(G, R34c); ctrlH_mul(G, R45);
        extractP(G, lbit[1], lbit[0], Cs);
#pragma unroll
        for (int j = 0; j < 4; ++j) {
            CcR[L][j] = packf(Cs[2*j], Cs[2*j]);
            CcI[L][j] = packf(-Cs[2*j+1], -Cs[2*j+1]);
        }
    }

    // gather source lanes + per-lane signs
    int srcZi = 26;
    if (lane == 7)  srcZi = 16;
    if (lane == 8)  srcZi = 24;
    if (lane == 9)  srcZi = 20;
    if (lane == 10) srcZi = 28;
    if (lane == 11) srcZi = 18;
    const int qsel = lane % 6;
    const int srcZr = (qsel==0)?10:(qsel==1)?0:(qsel==2)?8:(qsel==3)?4:(qsel==4)?12:2;
    const int srcF  = (qsel==0)?0:(32 >> qsel);
    float sgm[5];
#pragma unroll
    for (int i = 1; i <= 5; ++i)
        sgm[i-1] = ((lane >> (5 - i)) & 1) ? -1.f : 1.f;

    const float*  angB = angles + (size_t)b * SEQ * 6;
    const float4* pkB  = g_pk   + (size_t)b * SEQ * 2;
    const float2* csB  = g_cs2  + (size_t)b * SEQ * 6;
    const float*  cwB  = g_cw   + (size_t)b * SEQ * 18;
    float*        outB = out    + (size_t)b * SEQ * 18;
    const float   Dme  = (lane < 18) ? Dv_in[lane] : 0.f;

    float4 f0 = __ldg(pkB + 0), f1 = __ldg(pkB + 1);
    float2 ecs = __ldg(csB + qsel);
    float cwv = (lane < 18) ? __ldg(cwB + lane) : 0.f;
    float xme = (lane < 18) ? __ldg(angB + qsel) : 0.f;

    float hcv[6] = {1.f,1.f,1.f,1.f,1.f,1.f};
    float hsv[6] = {0.f,0.f,0.f,0.f,0.f,0.f};

#pragma unroll 1
    for (int t = 0; t < SEQ; ++t) {
        const int tn = (t + 1 < SEQ) ? t + 1 : t;
        float4 f0n = __ldg(pkB + tn*2 + 0), f1n = __ldg(pkB + tn*2 + 1);
        float2 ecsn = __ldg(csB + tn*6 + qsel);
        float cwn = (lane < 18) ? __ldg(cwB + tn*18 + lane) : 0.f;
        float xmn = (lane < 18) ? __ldg(angB + tn*6 + qsel) : 0.f;

        float dta[6] = {f0.x, f0.y, f0.z, f0.w, f1.x, f1.y};

        // QSVT phase
        float acc0 = B0[0] * dta[0], acc1 = B1[0] * dta[0];
#pragma unroll
        for (int i = 1; i < 6; ++i) {
            acc0 = fmaf(B0[i], dta[i], acc0);
            acc1 = fmaf(B1[i], dta[i], acc1);
        }
        float c0, s0, c1, s1;
        __sincosf(acc0, &s0, &c0);
        __sincosf(acc1, &s1, &c1);

        // initial product state at sigma^{-4}
        float pr0 = 1.f, pr1 = 1.f;
#pragma unroll
        for (int i = 0; i < 6; ++i) {
            pr0 *= ((s40 >> (5 - i)) & 1) ? hsv[i] : hcv[i];
            pr1 *= ((s41 >> (5 - i)) & 1) ? hsv[i] : hcv[i];
        }
        float r0 = pr0 * c0, i0 = pr0 * s0;
        float r1 = pr1 * c1, i1 = pr1 * s1;

        // ---- ansatz: 2 layers, packed mid-section ----
#pragma unroll
        for (int L = 0; L < 2; ++L) {
            applyA(r0, i0, r1, i1, 16, Aa[L], Ab[L]);
            ull P = packf(r0, r1), Q = packf(i0, i1);
            applyP2(P, Q, 8, 4, BcR[L], BcI[L]);
            applyP2(P, Q, 2, 1, CcR[L], CcI[L]);
            crx_gen2(P, Q, 2,  gCP[L*4+0], gSP[L*4+0]);
            crx_gen2(P, Q, 4,  gCP[L*4+1], gSP[L*4+1]);
            crx_gen2(P, Q, 8,  gCP[L*4+2], gSP[L*4+2]);
            crx_gen2(P, Q, 16, gCP[L*4+3], gSP[L*4+3]);
            crx_treg2(P, Q, tCP[L], tSP[L]);
            unpackf(P, r0, r1);
            unpackf(Q, i0, i1);
            crx_cb5(r1, i1, 1, C5c[L], C5s[L]);
        }

        // ---- measurements ----
        float w0 = r0*r0 + i0*i0;
        float w1 = r1*r1 + i1*i1;
        float ws = w0 + w1, wd = w0 - w1;
        float f = ws;
#pragma unroll
        for (int st = 0; st < 5; ++st) {
            int m = 16 >> st;
            float p = SH(f, m);
            f = (lane & m) ? (p - f) : (f + p);
        }

        float vr[5], vi[5];
#pragma unroll
        for (int i = 1; i <= 5; ++i) {
            int m = 1 << (5 - i);
            float pr0s = SH(r0, m), pi0s = SH(i0, m), pr1s = SH(r1, m), pi1s = SH(i1, m);
            float u = r0*pr0s + i0*pi0s + r1*pr1s + i1*pi1s;
            float v = r0*pi0s - i0*pr0s + r1*pi1s - i1*pr1s;
            vr[i-1] = u;
            vi[i-1] = sgm[i-1] * v;
        }
        float zr0 = r0*r1 + i0*i1;  zr0 += zr0;
        float zi0 = r0*i1 - i0*r1;  zi0 += zi0;

        float P1, P2, P3, P4, P5, P6, P7;
        { float a = vr[0] + SH(vr[0],16), bb = vi[0] + SH(vi[0],16); P1 = (lane&16) ? bb : a; }
        { float a = vr[1] + SH(vr[1],16), bb = vi[1] + SH(vi[1],16); P2 = (lane&16) ? bb : a; }
        { float a = vr[2] + SH(vr[2],16), bb = vi[2] + SH(vi[2],16); P3 = (lane&16) ? bb : a; }
        { float a = vr[3] + SH(vr[3],16), bb = vi[3] + SH(vi[3],16); P4 = (lane&16) ? bb : a; }
        { float a = vr[4] + SH(vr[4],16), bb = vi[4] + SH(vi[4],16); P5 = (lane&16) ? bb : a; }
        { float a = zr0   + SH(zr0,  16), bb = zi0   + SH(zi0,  16); P6 = (lane&16) ? bb : a; }
        P7 = wd + SH(wd, 16);
        float Q1, Q2, Q3, Q4;
        { float a = P1 + SH(P1,8), bb = P2 + SH(P2,8); Q1 = (lane&8) ? bb : a; }
        { float a = P3 + SH(P3,8), bb = P4 + SH(P4,8); Q2 = (lane&8) ? bb : a; }
        { float a = P5 + SH(P5,8), bb = P6 + SH(P6,8); Q3 = (lane&8) ? bb : a; }
        Q4 = P7 + SH(P7, 8);
        float R1, R2;
        { float a = Q1 + SH(Q1,4), bb = Q2 + SH(Q2,4); R1 = (lane&4) ? bb : a; }
        { float a = Q3 + SH(Q3,4), bb = Q4 + SH(Q4,4); R2 = (lane&4) ? bb : a; }
        float Sv;
        { float a = R1 + SH(R1,2), bb = R2 + SH(R2,2); Sv = (lane&2) ? bb : a; }
        Sv += SH(Sv, 1);

        float tF  = __shfl_sync(FULLM, f,  srcF);
        float tW  = __shfl_sync(FULLM, Sv, 6);
        float ztsel = qsel ? tF : tW;
        float zrsel = __shfl_sync(FULLM, Sv, srcZr);
        float giZ   = __shfl_sync(FULLM, Sv, srcZi);
        float csel = ecs.x, ssel = ecs.y;

        float hq   = csel * ztsel - ssel * zrsel;
        float mval = (lane < 6)  ? fmaf(csel, zrsel, ssel * ztsel)
                   : (lane < 12) ? giZ
                                 : hq;
        if (lane < 18)
            outB[t * 18 + lane] = cwv * mval + Dme * xme;

        float hs_, hc_;
        __sincosf(0.5f * hq, &hs_, &hc_);
#pragma unroll
        for (int i = 0; i < 6; ++i) {
            hcv[i] = __shfl_sync(FULLM, hc_, i);
            hsv[i] = __shfl_sync(FULLM, hs_, i);
        }

        f0 = f0n; f1 = f1n; ecs = ecsn; cwv = cwn; xme = xmn;
    }
}

// ---------------- launch ----------------
extern "C" void kernel_launch(void* const* d_in, const int* in_sizes, int n_in,
                              void* d_out, int out_size) {
    const float* angles = (const float*)d_in[0];
    const float* Wx     = (const float*)d_in[1];
    const float* Wdt    = (const float*)d_in[2];
    const float* bdt    = (const float*)d_in[3];
    const float* pc     = (const float*)d_in[4];
    const float* qp     = (const float*)d_in[5];
    const float* cp     = (const float*)d_in[6];
    const float* D      = (const float*)d_in[7];
    const float* Wc     = (const float*)d_in[8];

    prep_kernel <<<(BATCH * SEQ + 255) / 256, 256>>>(angles, Wx, Wdt, bdt, Wc);
    prep2_kernel<<<1, 64>>>(pc, qp, cp);
    sim_kernel  <<<BATCH, 32>>>(angles, D, (float*)d_out);
}